// round 8
// baseline (speedup 1.0000x reference)
#include <cuda_runtime.h>
#include <cuda_fp16.h>
#include <math_constants.h>

#define N_NODES 100000
#define N_EDGES 200000
#define NG      2000
#define H       32

typedef unsigned long long ull;

// ---------------- device scratch (alloc-free) ----------------
__device__ float  g_h[N_NODES * H];                 // node hidden fp32  12.8 MB
__device__ __half g_hh[N_NODES * H];                // node hidden fp16   6.4 MB
__device__ float  g_m[N_NODES * H];                 // aggregated msgs   12.8 MB
__device__ __half g_rh[(size_t)N_EDGES * 64];       // edge hidden fp16  25.6 MB
__device__ __half g_W2h[1024 * 64];                 // W2 fp16 transposed [n][k], 128 KB
__device__ float  g_sh[NG * H];                     // set2set h
__device__ float  g_sc[NG * H];                     // set2set c
__device__ float  g_rr[NG * H];                     // readout r
__device__ int    g_offs[NG + 1];                   // graph segment offsets

// ---------------- helpers ----------------
__device__ __forceinline__ ull pk2(float x) {
    ull r; asm("mov.b64 %0, {%1, %1};" : "=l"(r) : "f"(x)); return r;
}
__device__ __forceinline__ ull pkab(float lo, float hi) {
    ull r; asm("mov.b64 %0, {%1, %2};" : "=l"(r) : "f"(lo), "f"(hi)); return r;
}
__device__ __forceinline__ ull fma2(ull a, ull b, ull c) {
    ull d; asm("fma.rn.f32x2 %0, %1, %2, %3;" : "=l"(d) : "l"(a), "l"(b), "l"(c)); return d;
}
__device__ __forceinline__ void unpk2(ull v, float& lo, float& hi) {
    asm("mov.b64 {%0, %1}, %2;" : "=f"(lo), "=f"(hi) : "l"(v));
}
__device__ __forceinline__ float warpMax(float v) {
    #pragma unroll
    for (int o = 16; o > 0; o >>= 1) v = fmaxf(v, __shfl_xor_sync(0xffffffffu, v, o));
    return v;
}
__device__ __forceinline__ float warpSum(float v) {
    #pragma unroll
    for (int o = 16; o > 0; o >>= 1) v += __shfl_xor_sync(0xffffffffu, v, o);
    return v;
}
__device__ __forceinline__ float sigm(float x) { return 1.0f / (1.0f + expf(-x)); }

// ---------------- zero (set2set state only) ----------------
__global__ void k_zero_s2s() {
    int i = blockIdx.x * blockDim.x + threadIdx.x;
    if (i < NG * H) { g_sh[i] = 0.0f; g_sc[i] = 0.0f; g_rr[i] = 0.0f; }
}

// ---------------- W2 pack: g_W2h[n][k] = fp16(W2[k][n]) ----------------
__global__ void k_packW2(const float* __restrict__ W2) {
    int i = blockIdx.x * blockDim.x + threadIdx.x;
    if (i >= 64 * 1024) return;
    int k = i >> 10, n = i & 1023;
    g_W2h[n * 64 + k] = __float2half_rn(W2[i]);
}

// ---------------- encoder: h = nf @ enc_W + enc_b; writes fp16 mirror; zeros m
__global__ void k_encode(const float* __restrict__ nf, const float* __restrict__ W,
                         const float* __restrict__ b) {
    __shared__ float sW[16 * 32];
    __shared__ float sb[32];
    int t = threadIdx.x;
    for (int i = t; i < 512; i += 256) sW[i] = W[i];
    if (t < 32) sb[t] = b[t];
    __syncthreads();
    int n = blockIdx.x * blockDim.x + t;
    if (n >= N_NODES) return;
    float x[16];
    const float4* p = (const float4*)(nf + (long long)n * 16);
    #pragma unroll
    for (int q = 0; q < 4; q++) {
        float4 v = p[q];
        x[q*4+0] = v.x; x[q*4+1] = v.y; x[q*4+2] = v.z; x[q*4+3] = v.w;
    }
    float hv[32];
    #pragma unroll
    for (int c = 0; c < 32; c++) {
        float acc = sb[c];
        #pragma unroll
        for (int d = 0; d < 16; d++) acc += x[d] * sW[d * 32 + c];
        hv[c] = acc;
    }
    float4* hp = (float4*)&g_h[n * 32];
    float4* mz = (float4*)&g_m[n * 32];
    __half2* hh = (__half2*)&g_hh[n * 32];
    #pragma unroll
    for (int q = 0; q < 8; q++) {
        hp[q] = make_float4(hv[q*4], hv[q*4+1], hv[q*4+2], hv[q*4+3]);
        mz[q] = make_float4(0.f, 0.f, 0.f, 0.f);
    }
    #pragma unroll
    for (int c2 = 0; c2 < 16; c2++)
        hh[c2] = __floats2half2_rn(hv[2*c2], hv[2*c2+1]);
}

// ---------------- edge hidden: rh = fp16(relu(ef @ e_W1 + e_b1)) ----------------
__global__ void k_edgehid(const float* __restrict__ ef, const float* __restrict__ W,
                          const float* __restrict__ b) {
    __shared__ float sW[8 * 64];
    __shared__ float sb[64];
    int t = threadIdx.x;
    for (int i = t; i < 512; i += 256) sW[i] = W[i];
    if (t < 64) sb[t] = b[t];
    __syncthreads();
    int e = blockIdx.x * blockDim.x + t;
    if (e >= N_EDGES) return;
    float x[8];
    const float4* p = (const float4*)(ef + (long long)e * 8);
    float4 v0 = p[0], v1 = p[1];
    x[0]=v0.x; x[1]=v0.y; x[2]=v0.z; x[3]=v0.w;
    x[4]=v1.x; x[5]=v1.y; x[6]=v1.z; x[7]=v1.w;
    float o[64];
    #pragma unroll
    for (int c = 0; c < 64; c++) {
        float acc = sb[c];
        #pragma unroll
        for (int d = 0; d < 8; d++) acc += x[d] * sW[d * 64 + c];
        o[c] = fmaxf(acc, 0.0f);
    }
    __half2* dst = (__half2*)&g_rh[(size_t)e * 64];
    #pragma unroll
    for (int c2 = 0; c2 < 32; c2++)
        dst[c2] = __floats2half2_rn(o[2 * c2], o[2 * c2 + 1]);
}

// ---------------- FUSED message pass: m[tgt] += (rh[e] @ W2 + b2) @ h[src] ------
// Per block: 128 edges. A computed per 128-col chunk via HMMA, consumed from
// registers. Scatter is two-phase: per-chunk results staged in sMsg (plain STS,
// each (row,i) written exactly once across chunks), then flushed with
// line-coalesced atomics (warp <-> edge, lanes <-> 32 consecutive floats).
// Dynamic smem (65 KB): Rs 18432 | Wt 18432 | Hs 10240 | sMsg 16896 | sTgt 512 | b2s 512
#define ROWP 72
#define HSTR 40
#define MSG_SMEM 65024
__global__ void __launch_bounds__(256) k_msg_fused(const int* __restrict__ ei,
                                                   const float* __restrict__ b2) {
    extern __shared__ unsigned char dsm[];
    __half* Rs   = (__half*)dsm;                       // [128][ROWP]
    __half* Wt   = (__half*)(dsm + 18432);             // [128][ROWP]
    __half* Hs   = (__half*)(dsm + 36864);             // [128][HSTR]
    float*  sMsg = (float*)(dsm + 47104);              // [128][33]
    int*    sTgt = (int*)(dsm + 64000);                // [128]
    float*  b2s  = (float*)(dsm + 64512);              // [128]

    int t    = threadIdx.x;
    int lane = t & 31;
    int wid  = t >> 5;
    int e0   = blockIdx.x * 128;

    // load rh tile [128 x 64] fp16
    #pragma unroll
    for (int i = 0; i < 4; i++) {
        int g   = t + 256 * i;
        int row = g >> 3;
        int kg  = g & 7;
        uint4 v = make_uint4(0u, 0u, 0u, 0u);
        int e = e0 + row;
        if (e < N_EDGES) v = *(const uint4*)&g_rh[(size_t)e * 64 + kg * 8];
        *(uint4*)&Rs[row * ROWP + kg * 8] = v;
    }
    // gather h[src] fp16 -> Hs; load tgt
    {
        int row = t >> 1, hf = t & 1;
        int e = e0 + row;
        bool ok = e < N_EDGES;
        int src = 0;
        if (ok) {
            src = ei[e];
            if (hf == 0) sTgt[row] = ei[N_EDGES + e];
        }
        const uint4* hp = (const uint4*)&g_hh[src * 32 + hf * 16];
        #pragma unroll
        for (int qq = 0; qq < 2; qq++) {
            uint4 v = ok ? hp[qq] : make_uint4(0u, 0u, 0u, 0u);
            *(uint4*)&Hs[row * HSTR + hf * 16 + qq * 8] = v;
        }
    }

    int warpM = (wid & 1) * 64;
    int warpN = (wid >> 1) * 32;
    int aRow  = warpM + (lane & 15);
    int aColB = (lane >> 4) << 3;
    int bRow  = warpN + (lane & 7) + ((lane >> 4) << 3);
    int bColB = ((lane >> 3) & 1) << 3;

    #pragma unroll 1
    for (int c = 0; c < 8; c++) {
        __syncthreads();
        // load W2 chunk [128 n x 64 k] fp16 (prepacked transposed, L2-resident)
        #pragma unroll
        for (int i = 0; i < 4; i++) {
            int g   = t + 256 * i;
            int row = g >> 3;
            int kg  = g & 7;
            *(uint4*)&Wt[row * ROWP + kg * 8] =
                *(const uint4*)&g_W2h[(size_t)(c * 128 + row) * 64 + kg * 8];
        }
        if (t < 128) b2s[t] = b2[c * 128 + t];
        __syncthreads();

        float acc[4][4][4];
        #pragma unroll
        for (int mt = 0; mt < 4; mt++)
            #pragma unroll
            for (int nt = 0; nt < 4; nt++)
                #pragma unroll
                for (int q = 0; q < 4; q++) acc[mt][nt][q] = 0.0f;

        #pragma unroll
        for (int ks = 0; ks < 4; ks++) {
            int k0 = ks * 16;
            unsigned a[4][4];
            #pragma unroll
            for (int mt = 0; mt < 4; mt++) {
                unsigned addr = (unsigned)__cvta_generic_to_shared(
                    &Rs[(aRow + mt * 16) * ROWP + k0 + aColB]);
                asm volatile("ldmatrix.sync.aligned.m8n8.x4.shared.b16 {%0,%1,%2,%3}, [%4];"
                             : "=r"(a[mt][0]), "=r"(a[mt][1]), "=r"(a[mt][2]), "=r"(a[mt][3])
                             : "r"(addr));
            }
            unsigned bf[4][2];
            #pragma unroll
            for (int p = 0; p < 2; p++) {
                unsigned addr = (unsigned)__cvta_generic_to_shared(
                    &Wt[(bRow + p * 16) * ROWP + k0 + bColB]);
                asm volatile("ldmatrix.sync.aligned.m8n8.x4.shared.b16 {%0,%1,%2,%3}, [%4];"
                             : "=r"(bf[2*p][0]), "=r"(bf[2*p][1]),
                               "=r"(bf[2*p+1][0]), "=r"(bf[2*p+1][1])
                             : "r"(addr));
            }
            #pragma unroll
            for (int mt = 0; mt < 4; mt++)
                #pragma unroll
                for (int nt = 0; nt < 4; nt++) {
                    asm volatile(
                        "mma.sync.aligned.m16n8k16.row.col.f32.f16.f16.f32 "
                        "{%0,%1,%2,%3}, {%4,%5,%6,%7}, {%8,%9}, {%0,%1,%2,%3};"
                        : "+f"(acc[mt][nt][0]), "+f"(acc[mt][nt][1]),
                          "+f"(acc[mt][nt][2]), "+f"(acc[mt][nt][3])
                        : "r"(a[mt][0]), "r"(a[mt][1]), "r"(a[mt][2]), "r"(a[mt][3]),
                          "r"(bf[nt][0]), "r"(bf[nt][1]));
                }
        }

        // bias
        #pragma unroll
        for (int nt = 0; nt < 4; nt++) {
            float2 bb = *(const float2*)&b2s[warpN + nt * 8 + (lane & 3) * 2];
            #pragma unroll
            for (int mt = 0; mt < 4; mt++) {
                acc[mt][nt][0] += bb.x; acc[mt][nt][1] += bb.y;
                acc[mt][nt][2] += bb.x; acc[mt][nt][3] += bb.y;
            }
        }

        // matvec over j within the warp; stage result in sMsg (no atomics)
        int i_out = 4 * c + (wid >> 1);
        const __half2* Hs2 = (const __half2*)Hs;
        #pragma unroll
        for (int mt = 0; mt < 4; mt++) {
            #pragma unroll
            for (int qh = 0; qh < 2; qh++) {
                int rowl = warpM + mt * 16 + (lane >> 2) + 8 * qh;
                float partial = 0.0f;
                #pragma unroll
                for (int nt = 0; nt < 4; nt++) {
                    float2 hf2 = __half22float2(Hs2[rowl * (HSTR/2) + nt * 4 + (lane & 3)]);
                    partial += acc[mt][nt][2 * qh + 0] * hf2.x;
                    partial += acc[mt][nt][2 * qh + 1] * hf2.y;
                }
                partial += __shfl_xor_sync(0xffffffffu, partial, 1);
                partial += __shfl_xor_sync(0xffffffffu, partial, 2);
                if ((lane & 3) == 0)
                    sMsg[rowl * 33 + i_out] = partial;
            }
        }
    }

    // coalesced flush: warp <-> edge, lanes <-> 32 consecutive g_m floats
    __syncthreads();
    #pragma unroll 1
    for (int idx = t; idx < 128 * 32; idx += 256) {
        int e = idx >> 5, i = idx & 31;
        if (e0 + e < N_EDGES)
            atomicAdd(&g_m[sTgt[e] * 32 + i], sMsg[e * 33 + i]);
    }
}

// ---------------- GRU cell (f32x2 k-pairs); writes fp16 mirror; re-zeros m ----
__global__ void __launch_bounds__(256) k_gru(const float* __restrict__ Wih,
                                             const float* __restrict__ Whh,
                                             const float* __restrict__ bih,
                                             const float* __restrict__ bhh) {
    __shared__ ull sWi2[3 * 16 * 32];
    __shared__ ull sWh2[3 * 16 * 32];
    __shared__ float sbi[96];
    __shared__ float sbh[96];
    int t = threadIdx.x;
    for (int i = t; i < 1536; i += 256) {
        int g  = i >> 9;
        int k2 = (i >> 5) & 15;
        int c  = i & 31;
        int k  = g * 32 + 2 * k2;
        sWi2[i] = pkab(Wih[k * 32 + c], Wih[(k + 1) * 32 + c]);
        sWh2[i] = pkab(Whh[k * 32 + c], Whh[(k + 1) * 32 + c]);
    }
    if (t < 96) { sbi[t] = bih[t]; sbh[t] = bhh[t]; }
    __syncthreads();
    int n = blockIdx.x * blockDim.x + t;
    if (n >= N_NODES) return;

    float mv[32], hv[32];
    const float4* mp = (const float4*)&g_m[n * 32];
    const float4* hp = (const float4*)&g_h[n * 32];
    #pragma unroll
    for (int q = 0; q < 8; q++) {
        float4 a = mp[q]; mv[q*4]=a.x; mv[q*4+1]=a.y; mv[q*4+2]=a.z; mv[q*4+3]=a.w;
        float4 b = hp[q]; hv[q*4]=b.x; hv[q*4+1]=b.y; hv[q*4+2]=b.z; hv[q*4+3]=b.w;
    }
    float4* mz = (float4*)&g_m[n * 32];
    #pragma unroll
    for (int q = 0; q < 8; q++) mz[q] = make_float4(0.f, 0.f, 0.f, 0.f);

    #pragma unroll 1
    for (int k2 = 0; k2 < 16; k2++) {
        int k = 2 * k2;
        ull accr = pkab(sbi[k] + sbh[k], sbi[k + 1] + sbh[k + 1]);
        ull accz = pkab(sbi[32 + k] + sbh[32 + k], sbi[33 + k] + sbh[33 + k]);
        ull accn = pkab(sbi[64 + k], sbi[65 + k]);
        ull acch = pkab(sbh[64 + k], sbh[65 + k]);
        const ull* wir = &sWi2[(0 * 16 + k2) * 32];
        const ull* wiz = &sWi2[(1 * 16 + k2) * 32];
        const ull* win = &sWi2[(2 * 16 + k2) * 32];
        const ull* whr = &sWh2[(0 * 16 + k2) * 32];
        const ull* whz = &sWh2[(1 * 16 + k2) * 32];
        const ull* whn = &sWh2[(2 * 16 + k2) * 32];
        #pragma unroll
        for (int c = 0; c < 32; c++) {
            ull pm = pk2(mv[c]);
            ull ph = pk2(hv[c]);
            accr = fma2(pm, wir[c], accr);
            accr = fma2(ph, whr[c], accr);
            accz = fma2(pm, wiz[c], accz);
            accz = fma2(ph, whz[c], accz);
            accn = fma2(pm, win[c], accn);
            acch = fma2(ph, whn[c], acch);
        }
        float rlo, rhi, zlo, zhi, nlo, nhi, hlo, hhi;
        unpk2(accr, rlo, rhi);
        unpk2(accz, zlo, zhi);
        unpk2(accn, nlo, nhi);
        unpk2(acch, hlo, hhi);
        float r0 = sigm(rlo), z0 = sigm(zlo);
        float n0 = tanhf(nlo + r0 * hlo);
        float r1 = sigm(rhi), z1 = sigm(zhi);
        float n1 = tanhf(nhi + r1 * hhi);
        float2 hnew;
        hnew.x = (1.0f - z0) * n0 + z0 * hv[k];
        hnew.y = (1.0f - z1) * n1 + z1 * hv[k + 1];
        *(float2*)&g_h[n * 32 + k] = hnew;
        *(__half2*)&g_hh[n * 32 + k] = __floats2half2_rn(hnew.x, hnew.y);
    }
}

// ---------------- graph segment offsets (batch_indices sorted) ----------------
__global__ void k_offs(const int* __restrict__ batch) {
    int n = blockIdx.x * blockDim.x + threadIdx.x;
    if (n >= N_NODES) return;
    int b = batch[n];
    int prev = (n == 0) ? -1 : batch[n - 1];
    for (int g = prev + 1; g <= b; g++) g_offs[g] = n;
    if (n == N_NODES - 1)
        for (int g = b + 1; g <= NG; g++) g_offs[g] = N_NODES;
}

// ---------------- Set2Set attention + readout (online softmax, warp/graph) ----
__global__ void __launch_bounds__(256) k_attend() {
    int lane = threadIdx.x & 31;
    int g = (blockIdx.x * blockDim.x + threadIdx.x) >> 5;
    if (g >= NG) return;
    int s = g_offs[g], tEnd = g_offs[g + 1];
    float q = g_sh[g * 32 + lane];
    float maxv = -CUDART_INF_F, denom = 0.0f, racc = 0.0f;

    for (int base = s; base < tEnd; base += 32) {
        int n = base + lane;
        bool act = n < tEnd;
        int nn = act ? n : s;
        float rv[32];
        const float4* hp4 = (const float4*)&g_h[nn * 32];
        #pragma unroll
        for (int q4 = 0; q4 < 8; q4++) {
            float4 v = hp4[q4];
            rv[q4*4] = v.x; rv[q4*4+1] = v.y; rv[q4*4+2] = v.z; rv[q4*4+3] = v.w;
        }
        float ev = 0.0f;
        #pragma unroll
        for (int j = 0; j < 32; j++)
            ev += rv[j] * __shfl_sync(0xffffffffu, q, j);
        float e_n = act ? ev : -CUDART_INF_F;
        float cm = warpMax(e_n);
        float nm = fmaxf(maxv, cm);
        float scale = (maxv == -CUDART_INF_F) ? 0.0f : expf(maxv - nm);
        float p = act ? expf(e_n - nm) : 0.0f;
        float ps = warpSum(p);
        denom = denom * scale + ps;
        racc *= scale;
        maxv = nm;
        int cnt = min(32, tEnd - base);
        for (int n2 = 0; n2 < cnt; n2++) {
            float pn = __shfl_sync(0xffffffffu, p, n2);
            racc += pn * g_h[(base + n2) * 32 + lane];
        }
    }
    g_rr[g * 32 + lane] = (denom > 0.0f) ? (racc / denom) : 0.0f;
}

// ---------------- Set2Set LSTM step (fused mini-GEMM, 64 graphs/block) --------
__global__ void __launch_bounds__(256) k_lstm(const float* __restrict__ Wih,
                                              const float* __restrict__ Whh,
                                              const float* __restrict__ bih,
                                              const float* __restrict__ bhh) {
    __shared__ float sx[64 * 64];
    __shared__ float sW[48 * 128];
    int t  = threadIdx.x;
    int g0 = blockIdx.x * 64;
    int k  = t & 31;
    int rg = t >> 5;

    for (int i = t; i < 64 * 64; i += 256) {
        int g = i >> 6, c = i & 63;
        int gg = g0 + g;
        float v = 0.0f;
        if (gg < NG) v = (c < 32) ? g_sh[gg * 32 + c] : g_rr[gg * 32 + (c - 32)];
        sx[i] = v;
    }

    float acc[8][4];
    #pragma unroll
    for (int r = 0; r < 8; r++)
        #pragma unroll
        for (int j = 0; j < 4; j++) acc[r][j] = 0.0f;

    #pragma unroll 1
    for (int kc = 0; kc < 2; kc++) {
        __syncthreads();
        for (int i = t; i < 48 * 128; i += 256) {
            int c  = kc * 48 + (i >> 7);
            int kk = i & 127;
            sW[i] = (c < 64) ? Wih[kk * 64 + c] : Whh[kk * 32 + (c - 64)];
        }
        __syncthreads();
        for (int cc = 0; cc < 48; cc++) {
            int c  = kc * 48 + cc;
            int cx = (c < 64) ? c : (c - 64);
            float b0 = sW[cc * 128 + k];
            float b1 = sW[cc * 128 + 32 + k];
            float b2v = sW[cc * 128 + 64 + k];
            float b3 = sW[cc * 128 + 96 + k];
            #pragma unroll
            for (int r = 0; r < 8; r++) {
                float a = sx[(rg * 8 + r) * 64 + cx];
                acc[r][0] += a * b0;
                acc[r][1] += a * b1;
                acc[r][2] += a * b2v;
                acc[r][3] += a * b3;
            }
        }
    }

    float bi0 = __ldg(&bih[k])      + __ldg(&bhh[k]);
    float bf  = __ldg(&bih[32 + k]) + __ldg(&bhh[32 + k]);
    float bg  = __ldg(&bih[64 + k]) + __ldg(&bhh[64 + k]);
    float bo  = __ldg(&bih[96 + k]) + __ldg(&bhh[96 + k]);
    #pragma unroll
    for (int r = 0; r < 8; r++) {
        int gg = g0 + rg * 8 + r;
        if (gg >= NG) break;
        float i_ = sigm(acc[r][0] + bi0);
        float f_ = sigm(acc[r][1] + bf);
        float gv = tanhf(acc[r][2] + bg);
        float o_ = sigm(acc[r][3] + bo);
        float cn = f_ * g_sc[gg * 32 + k] + i_ * gv;
        g_sc[gg * 32 + k] = cn;
        g_sh[gg * 32 + k] = o_ * tanhf(cn);
    }
}

// ---------------- output head ----------------
__global__ void k_output(const float* __restrict__ W1, const float* __restrict__ b1,
                         const float* __restrict__ W2, const float* __restrict__ b2,
                         float* __restrict__ out) {
    int g = blockIdx.x * blockDim.x + threadIdx.x;
    if (g >= NG) return;
    float emb[64];
    #pragma unroll
    for (int c = 0; c < 32; c++) {
        emb[c]      = g_sh[g * 32 + c];
        emb[32 + c] = g_rr[g * 32 + c];
    }
    float hid[32];
    #pragma unroll
    for (int c = 0; c < 32; c++) {
        float acc = __ldg(&b1[c]);
        #pragma unroll
        for (int d = 0; d < 64; d++) acc += emb[d] * __ldg(&W1[d * 32 + c]);
        hid[c] = fmaxf(acc, 0.0f);
    }
    #pragma unroll
    for (int kk = 0; kk < 3; kk++) {
        float acc = __ldg(&b2[kk]);
        #pragma unroll
        for (int c = 0; c < 32; c++) acc += hid[c] * __ldg(&W2[c * 3 + kk]);
        out[g * 3 + kk] = acc;
    }
}

// ---------------- launch ----------------
extern "C" void kernel_launch(void* const* d_in, const int* in_sizes, int n_in,
                              void* d_out, int out_size) {
    const float* nf     = (const float*)d_in[0];
    const float* ef     = (const float*)d_in[1];
    const float* enc_W  = (const float*)d_in[2];
    const float* enc_b  = (const float*)d_in[3];
    const float* e_W1   = (const float*)d_in[4];
    const float* e_b1   = (const float*)d_in[5];
    const float* e_W2   = (const float*)d_in[6];
    const float* e_b2   = (const float*)d_in[7];
    const float* gWih   = (const float*)d_in[8];
    const float* gWhh   = (const float*)d_in[9];
    const float* gbih   = (const float*)d_in[10];
    const float* gbhh   = (const float*)d_in[11];
    const float* lWih   = (const float*)d_in[12];
    const float* lWhh   = (const float*)d_in[13];
    const float* lbih   = (const float*)d_in[14];
    const float* lbhh   = (const float*)d_in[15];
    const float* oW1    = (const float*)d_in[16];
    const float* ob1    = (const float*)d_in[17];
    const float* oW2    = (const float*)d_in[18];
    const float* ob2    = (const float*)d_in[19];
    const int*   eidx   = (const int*)d_in[20];
    const int*   batch  = (const int*)d_in[21];
    float* out = (float*)d_out;

    cudaFuncSetAttribute(k_msg_fused, cudaFuncAttributeMaxDynamicSharedMemorySize,
                         MSG_SMEM);

    // order chosen so the 4th launch (ncu capture target) is k_msg_fused
    k_packW2<<<(64 * 1024 + 255) / 256, 256>>>(e_W2);
    k_encode<<<(N_NODES + 255) / 256, 256>>>(nf, enc_W, enc_b);
    k_edgehid<<<(N_EDGES + 255) / 256, 256>>>(ef, e_W1, e_b1);

    for (int r = 0; r < 3; r++) {
        k_msg_fused<<<(N_EDGES + 127) / 128, 256, MSG_SMEM>>>(eidx, e_b2);
        k_gru<<<(N_NODES + 255) / 256, 256>>>(gWih, gWhh, gbih, gbhh);
    }

    k_zero_s2s<<<(NG * H + 255) / 256, 256>>>();
    k_offs<<<(N_NODES + 255) / 256, 256>>>(batch);

    for (int s = 0; s < 4; s++) {
        k_attend<<<(NG * 32 + 255) / 256, 256>>>();
        k_lstm<<<(NG + 63) / 64, 256>>>(lWih, lWhh, lbih, lbhh);
    }

    k_output<<<(NG + 255) / 256, 256>>>(oW1, ob1, oW2, ob2, out);
}

// round 9
// speedup vs baseline: 1.1168x; 1.1168x over previous
#include <cuda_runtime.h>
#include <cuda_fp16.h>
#include <math_constants.h>

#define N_NODES 100000
#define N_EDGES 200000
#define NG      2000
#define H       32

typedef unsigned long long ull;

// ---------------- device scratch (alloc-free) ----------------
__device__ float  g_h[N_NODES * H];                 // node hidden fp32  12.8 MB
__device__ __half g_hh[N_NODES * H];                // node hidden fp16   6.4 MB
__device__ float  g_m[N_NODES * H];                 // aggregated msgs   12.8 MB
__device__ __half g_rh[(size_t)N_EDGES * 64];       // edge hidden fp16  25.6 MB
__device__ __half g_W2h[1024 * 64];                 // W2 fp16 transposed [n][k], 128 KB
__device__ float  g_sh[NG * H];                     // set2set h
__device__ float  g_sc[NG * H];                     // set2set c
__device__ float  g_rr[NG * H];                     // readout r
__device__ int    g_offs[NG + 1];                   // graph segment offsets

// ---------------- helpers ----------------
__device__ __forceinline__ ull pk2(float x) {
    ull r; asm("mov.b64 %0, {%1, %1};" : "=l"(r) : "f"(x)); return r;
}
__device__ __forceinline__ ull pkab(float lo, float hi) {
    ull r; asm("mov.b64 %0, {%1, %2};" : "=l"(r) : "f"(lo), "f"(hi)); return r;
}
__device__ __forceinline__ ull fma2(ull a, ull b, ull c) {
    ull d; asm("fma.rn.f32x2 %0, %1, %2, %3;" : "=l"(d) : "l"(a), "l"(b), "l"(c)); return d;
}
__device__ __forceinline__ void unpk2(ull v, float& lo, float& hi) {
    asm("mov.b64 {%0, %1}, %2;" : "=f"(lo), "=f"(hi) : "l"(v));
}
__device__ __forceinline__ float warpMax(float v) {
    #pragma unroll
    for (int o = 16; o > 0; o >>= 1) v = fmaxf(v, __shfl_xor_sync(0xffffffffu, v, o));
    return v;
}
__device__ __forceinline__ float warpSum(float v) {
    #pragma unroll
    for (int o = 16; o > 0; o >>= 1) v += __shfl_xor_sync(0xffffffffu, v, o);
    return v;
}
__device__ __forceinline__ float sigm(float x) { return 1.0f / (1.0f + expf(-x)); }

// ---------------- zero (set2set state only) ----------------
__global__ void k_zero_s2s() {
    int i = blockIdx.x * blockDim.x + threadIdx.x;
    if (i < NG * H) { g_sh[i] = 0.0f; g_sc[i] = 0.0f; g_rr[i] = 0.0f; }
}

// ---------------- W2 pack: g_W2h[n][k] = fp16(W2[k][n]) ----------------
__global__ void k_packW2(const float* __restrict__ W2) {
    int i = blockIdx.x * blockDim.x + threadIdx.x;
    if (i >= 64 * 1024) return;
    int k = i >> 10, n = i & 1023;
    g_W2h[n * 64 + k] = __float2half_rn(W2[i]);
}

// ---------------- encoder: h = nf @ enc_W + enc_b; writes fp16 mirror; zeros m
__global__ void k_encode(const float* __restrict__ nf, const float* __restrict__ W,
                         const float* __restrict__ b) {
    __shared__ float sW[16 * 32];
    __shared__ float sb[32];
    int t = threadIdx.x;
    for (int i = t; i < 512; i += 256) sW[i] = W[i];
    if (t < 32) sb[t] = b[t];
    __syncthreads();
    int n = blockIdx.x * blockDim.x + t;
    if (n >= N_NODES) return;
    float x[16];
    const float4* p = (const float4*)(nf + (long long)n * 16);
    #pragma unroll
    for (int q = 0; q < 4; q++) {
        float4 v = p[q];
        x[q*4+0] = v.x; x[q*4+1] = v.y; x[q*4+2] = v.z; x[q*4+3] = v.w;
    }
    float hv[32];
    #pragma unroll
    for (int c = 0; c < 32; c++) {
        float acc = sb[c];
        #pragma unroll
        for (int d = 0; d < 16; d++) acc += x[d] * sW[d * 32 + c];
        hv[c] = acc;
    }
    float4* hp = (float4*)&g_h[n * 32];
    float4* mz = (float4*)&g_m[n * 32];
    __half2* hh = (__half2*)&g_hh[n * 32];
    #pragma unroll
    for (int q = 0; q < 8; q++) {
        hp[q] = make_float4(hv[q*4], hv[q*4+1], hv[q*4+2], hv[q*4+3]);
        mz[q] = make_float4(0.f, 0.f, 0.f, 0.f);
    }
    #pragma unroll
    for (int c2 = 0; c2 < 16; c2++)
        hh[c2] = __floats2half2_rn(hv[2*c2], hv[2*c2+1]);
}

// ---------------- edge hidden: rh = fp16(relu(ef @ e_W1 + e_b1)) ----------------
__global__ void k_edgehid(const float* __restrict__ ef, const float* __restrict__ W,
                          const float* __restrict__ b) {
    __shared__ float sW[8 * 64];
    __shared__ float sb[64];
    int t = threadIdx.x;
    for (int i = t; i < 512; i += 256) sW[i] = W[i];
    if (t < 64) sb[t] = b[t];
    __syncthreads();
    int e = blockIdx.x * blockDim.x + t;
    if (e >= N_EDGES) return;
    float x[8];
    const float4* p = (const float4*)(ef + (long long)e * 8);
    float4 v0 = p[0], v1 = p[1];
    x[0]=v0.x; x[1]=v0.y; x[2]=v0.z; x[3]=v0.w;
    x[4]=v1.x; x[5]=v1.y; x[6]=v1.z; x[7]=v1.w;
    float o[64];
    #pragma unroll
    for (int c = 0; c < 64; c++) {
        float acc = sb[c];
        #pragma unroll
        for (int d = 0; d < 8; d++) acc += x[d] * sW[d * 64 + c];
        o[c] = fmaxf(acc, 0.0f);
    }
    __half2* dst = (__half2*)&g_rh[(size_t)e * 64];
    #pragma unroll
    for (int c2 = 0; c2 < 32; c2++)
        dst[c2] = __floats2half2_rn(o[2 * c2], o[2 * c2 + 1]);
}

// ---------------- FUSED message pass: m[tgt] += (rh[e] @ W2 + b2) @ h[src] ------
// Per block: 128 edges. A computed per 128-col chunk via HMMA, consumed from
// registers. Scatter is two-phase: per-chunk results staged in sMsg (plain STS,
// each (row,i) written exactly once across chunks), then flushed with
// line-coalesced atomics (warp <-> edge, lanes <-> 32 consecutive floats).
// __launch_bounds__(256, 2): cap regs at 128 so 2 blocks/SM fit the 64K RF.
// Dynamic smem (65 KB): Rs 18432 | Wt 18432 | Hs 10240 | sMsg 16896 | sTgt 512 | b2s 512
#define ROWP 72
#define HSTR 40
#define MSG_SMEM 65024
__global__ void __launch_bounds__(256, 2) k_msg_fused(const int* __restrict__ ei,
                                                      const float* __restrict__ b2) {
    extern __shared__ unsigned char dsm[];
    __half* Rs   = (__half*)dsm;                       // [128][ROWP]
    __half* Wt   = (__half*)(dsm + 18432);             // [128][ROWP]
    __half* Hs   = (__half*)(dsm + 36864);             // [128][HSTR]
    float*  sMsg = (float*)(dsm + 47104);              // [128][33]
    int*    sTgt = (int*)(dsm + 64000);                // [128]
    float*  b2s  = (float*)(dsm + 64512);              // [128]

    int t    = threadIdx.x;
    int lane = t & 31;
    int wid  = t >> 5;
    int e0   = blockIdx.x * 128;

    // load rh tile [128 x 64] fp16
    #pragma unroll
    for (int i = 0; i < 4; i++) {
        int g   = t + 256 * i;
        int row = g >> 3;
        int kg  = g & 7;
        uint4 v = make_uint4(0u, 0u, 0u, 0u);
        int e = e0 + row;
        if (e < N_EDGES) v = *(const uint4*)&g_rh[(size_t)e * 64 + kg * 8];
        *(uint4*)&Rs[row * ROWP + kg * 8] = v;
    }
    // gather h[src] fp16 -> Hs; load tgt
    {
        int row = t >> 1, hf = t & 1;
        int e = e0 + row;
        bool ok = e < N_EDGES;
        int src = 0;
        if (ok) {
            src = ei[e];
            if (hf == 0) sTgt[row] = ei[N_EDGES + e];
        }
        const uint4* hp = (const uint4*)&g_hh[src * 32 + hf * 16];
        #pragma unroll
        for (int qq = 0; qq < 2; qq++) {
            uint4 v = ok ? hp[qq] : make_uint4(0u, 0u, 0u, 0u);
            *(uint4*)&Hs[row * HSTR + hf * 16 + qq * 8] = v;
        }
    }

    int warpM = (wid & 1) * 64;
    int warpN = (wid >> 1) * 32;
    int aRow  = warpM + (lane & 15);
    int aColB = (lane >> 4) << 3;
    int bRow  = warpN + (lane & 7) + ((lane >> 4) << 3);
    int bColB = ((lane >> 3) & 1) << 3;

    #pragma unroll 1
    for (int c = 0; c < 8; c++) {
        __syncthreads();
        // load W2 chunk [128 n x 64 k] fp16 (prepacked transposed, L2-resident)
        #pragma unroll
        for (int i = 0; i < 4; i++) {
            int g   = t + 256 * i;
            int row = g >> 3;
            int kg  = g & 7;
            *(uint4*)&Wt[row * ROWP + kg * 8] =
                *(const uint4*)&g_W2h[(size_t)(c * 128 + row) * 64 + kg * 8];
        }
        if (t < 128) b2s[t] = b2[c * 128 + t];
        __syncthreads();

        float acc[4][4][4];
        #pragma unroll
        for (int mt = 0; mt < 4; mt++)
            #pragma unroll
            for (int nt = 0; nt < 4; nt++)
                #pragma unroll
                for (int q = 0; q < 4; q++) acc[mt][nt][q] = 0.0f;

        #pragma unroll
        for (int ks = 0; ks < 4; ks++) {
            int k0 = ks * 16;
            unsigned a[4][4];
            #pragma unroll
            for (int mt = 0; mt < 4; mt++) {
                unsigned addr = (unsigned)__cvta_generic_to_shared(
                    &Rs[(aRow + mt * 16) * ROWP + k0 + aColB]);
                asm volatile("ldmatrix.sync.aligned.m8n8.x4.shared.b16 {%0,%1,%2,%3}, [%4];"
                             : "=r"(a[mt][0]), "=r"(a[mt][1]), "=r"(a[mt][2]), "=r"(a[mt][3])
                             : "r"(addr));
            }
            unsigned bf[4][2];
            #pragma unroll
            for (int p = 0; p < 2; p++) {
                unsigned addr = (unsigned)__cvta_generic_to_shared(
                    &Wt[(bRow + p * 16) * ROWP + k0 + bColB]);
                asm volatile("ldmatrix.sync.aligned.m8n8.x4.shared.b16 {%0,%1,%2,%3}, [%4];"
                             : "=r"(bf[2*p][0]), "=r"(bf[2*p][1]),
                               "=r"(bf[2*p+1][0]), "=r"(bf[2*p+1][1])
                             : "r"(addr));
            }
            #pragma unroll
            for (int mt = 0; mt < 4; mt++)
                #pragma unroll
                for (int nt = 0; nt < 4; nt++) {
                    asm volatile(
                        "mma.sync.aligned.m16n8k16.row.col.f32.f16.f16.f32 "
                        "{%0,%1,%2,%3}, {%4,%5,%6,%7}, {%8,%9}, {%0,%1,%2,%3};"
                        : "+f"(acc[mt][nt][0]), "+f"(acc[mt][nt][1]),
                          "+f"(acc[mt][nt][2]), "+f"(acc[mt][nt][3])
                        : "r"(a[mt][0]), "r"(a[mt][1]), "r"(a[mt][2]), "r"(a[mt][3]),
                          "r"(bf[nt][0]), "r"(bf[nt][1]));
                }
        }

        // bias
        #pragma unroll
        for (int nt = 0; nt < 4; nt++) {
            float2 bb = *(const float2*)&b2s[warpN + nt * 8 + (lane & 3) * 2];
            #pragma unroll
            for (int mt = 0; mt < 4; mt++) {
                acc[mt][nt][0] += bb.x; acc[mt][nt][1] += bb.y;
                acc[mt][nt][2] += bb.x; acc[mt][nt][3] += bb.y;
            }
        }

        // matvec over j within the warp; stage result in sMsg (no atomics)
        int i_out = 4 * c + (wid >> 1);
        const __half2* Hs2 = (const __half2*)Hs;
        #pragma unroll
        for (int mt = 0; mt < 4; mt++) {
            #pragma unroll
            for (int qh = 0; qh < 2; qh++) {
                int rowl = warpM + mt * 16 + (lane >> 2) + 8 * qh;
                float partial = 0.0f;
                #pragma unroll
                for (int nt = 0; nt < 4; nt++) {
                    float2 hf2 = __half22float2(Hs2[rowl * (HSTR/2) + nt * 4 + (lane & 3)]);
                    partial += acc[mt][nt][2 * qh + 0] * hf2.x;
                    partial += acc[mt][nt][2 * qh + 1] * hf2.y;
                }
                partial += __shfl_xor_sync(0xffffffffu, partial, 1);
                partial += __shfl_xor_sync(0xffffffffu, partial, 2);
                if ((lane & 3) == 0)
                    sMsg[rowl * 33 + i_out] = partial;
            }
        }
    }

    // coalesced flush: warp <-> edge, lanes <-> 32 consecutive g_m floats
    __syncthreads();
    #pragma unroll 1
    for (int idx = t; idx < 128 * 32; idx += 256) {
        int e = idx >> 5, i = idx & 31;
        if (e0 + e < N_EDGES)
            atomicAdd(&g_m[sTgt[e] * 32 + i], sMsg[e * 33 + i]);
    }
}

// ---------------- GRU cell (f32x2 k-pairs); writes fp16 mirror; re-zeros m ----
__global__ void __launch_bounds__(256) k_gru(const float* __restrict__ Wih,
                                             const float* __restrict__ Whh,
                                             const float* __restrict__ bih,
                                             const float* __restrict__ bhh) {
    __shared__ ull sWi2[3 * 16 * 32];
    __shared__ ull sWh2[3 * 16 * 32];
    __shared__ float sbi[96];
    __shared__ float sbh[96];
    int t = threadIdx.x;
    for (int i = t; i < 1536; i += 256) {
        int g  = i >> 9;
        int k2 = (i >> 5) & 15;
        int c  = i & 31;
        int k  = g * 32 + 2 * k2;
        sWi2[i] = pkab(Wih[k * 32 + c], Wih[(k + 1) * 32 + c]);
        sWh2[i] = pkab(Whh[k * 32 + c], Whh[(k + 1) * 32 + c]);
    }
    if (t < 96) { sbi[t] = bih[t]; sbh[t] = bhh[t]; }
    __syncthreads();
    int n = blockIdx.x * blockDim.x + t;
    if (n >= N_NODES) return;

    float mv[32], hv[32];
    const float4* mp = (const float4*)&g_m[n * 32];
    const float4* hp = (const float4*)&g_h[n * 32];
    #pragma unroll
    for (int q = 0; q < 8; q++) {
        float4 a = mp[q]; mv[q*4]=a.x; mv[q*4+1]=a.y; mv[q*4+2]=a.z; mv[q*4+3]=a.w;
        float4 b = hp[q]; hv[q*4]=b.x; hv[q*4+1]=b.y; hv[q*4+2]=b.z; hv[q*4+3]=b.w;
    }
    float4* mz = (float4*)&g_m[n * 32];
    #pragma unroll
    for (int q = 0; q < 8; q++) mz[q] = make_float4(0.f, 0.f, 0.f, 0.f);

    #pragma unroll 1
    for (int k2 = 0; k2 < 16; k2++) {
        int k = 2 * k2;
        ull accr = pkab(sbi[k] + sbh[k], sbi[k + 1] + sbh[k + 1]);
        ull accz = pkab(sbi[32 + k] + sbh[32 + k], sbi[33 + k] + sbh[33 + k]);
        ull accn = pkab(sbi[64 + k], sbi[65 + k]);
        ull acch = pkab(sbh[64 + k], sbh[65 + k]);
        const ull* wir = &sWi2[(0 * 16 + k2) * 32];
        const ull* wiz = &sWi2[(1 * 16 + k2) * 32];
        const ull* win = &sWi2[(2 * 16 + k2) * 32];
        const ull* whr = &sWh2[(0 * 16 + k2) * 32];
        const ull* whz = &sWh2[(1 * 16 + k2) * 32];
        const ull* whn = &sWh2[(2 * 16 + k2) * 32];
        #pragma unroll
        for (int c = 0; c < 32; c++) {
            ull pm = pk2(mv[c]);
            ull ph = pk2(hv[c]);
            accr = fma2(pm, wir[c], accr);
            accr = fma2(ph, whr[c], accr);
            accz = fma2(pm, wiz[c], accz);
            accz = fma2(ph, whz[c], accz);
            accn = fma2(pm, win[c], accn);
            acch = fma2(ph, whn[c], acch);
        }
        float rlo, rhi, zlo, zhi, nlo, nhi, hlo, hhi;
        unpk2(accr, rlo, rhi);
        unpk2(accz, zlo, zhi);
        unpk2(accn, nlo, nhi);
        unpk2(acch, hlo, hhi);
        float r0 = sigm(rlo), z0 = sigm(zlo);
        float n0 = tanhf(nlo + r0 * hlo);
        float r1 = sigm(rhi), z1 = sigm(zhi);
        float n1 = tanhf(nhi + r1 * hhi);
        float2 hnew;
        hnew.x = (1.0f - z0) * n0 + z0 * hv[k];
        hnew.y = (1.0f - z1) * n1 + z1 * hv[k + 1];
        *(float2*)&g_h[n * 32 + k] = hnew;
        *(__half2*)&g_hh[n * 32 + k] = __floats2half2_rn(hnew.x, hnew.y);
    }
}

// ---------------- graph segment offsets (batch_indices sorted) ----------------
__global__ void k_offs(const int* __restrict__ batch) {
    int n = blockIdx.x * blockDim.x + threadIdx.x;
    if (n >= N_NODES) return;
    int b = batch[n];
    int prev = (n == 0) ? -1 : batch[n - 1];
    for (int g = prev + 1; g <= b; g++) g_offs[g] = n;
    if (n == N_NODES - 1)
        for (int g = b + 1; g <= NG; g++) g_offs[g] = N_NODES;
}

// ---------------- Set2Set attention + readout (online softmax, warp/graph) ----
__global__ void __launch_bounds__(256) k_attend() {
    int lane = threadIdx.x & 31;
    int g = (blockIdx.x * blockDim.x + threadIdx.x) >> 5;
    if (g >= NG) return;
    int s = g_offs[g], tEnd = g_offs[g + 1];
    float q = g_sh[g * 32 + lane];
    float maxv = -CUDART_INF_F, denom = 0.0f, racc = 0.0f;

    for (int base = s; base < tEnd; base += 32) {
        int n = base + lane;
        bool act = n < tEnd;
        int nn = act ? n : s;
        float rv[32];
        const float4* hp4 = (const float4*)&g_h[nn * 32];
        #pragma unroll
        for (int q4 = 0; q4 < 8; q4++) {
            float4 v = hp4[q4];
            rv[q4*4] = v.x; rv[q4*4+1] = v.y; rv[q4*4+2] = v.z; rv[q4*4+3] = v.w;
        }
        float ev = 0.0f;
        #pragma unroll
        for (int j = 0; j < 32; j++)
            ev += rv[j] * __shfl_sync(0xffffffffu, q, j);
        float e_n = act ? ev : -CUDART_INF_F;
        float cm = warpMax(e_n);
        float nm = fmaxf(maxv, cm);
        float scale = (maxv == -CUDART_INF_F) ? 0.0f : expf(maxv - nm);
        float p = act ? expf(e_n - nm) : 0.0f;
        float ps = warpSum(p);
        denom = denom * scale + ps;
        racc *= scale;
        maxv = nm;
        int cnt = min(32, tEnd - base);
        for (int n2 = 0; n2 < cnt; n2++) {
            float pn = __shfl_sync(0xffffffffu, p, n2);
            racc += pn * g_h[(base + n2) * 32 + lane];
        }
    }
    g_rr[g * 32 + lane] = (denom > 0.0f) ? (racc / denom) : 0.0f;
}

// ---------------- Set2Set LSTM step (fused mini-GEMM, 64 graphs/block) --------
__global__ void __launch_bounds__(256) k_lstm(const float* __restrict__ Wih,
                                              const float* __restrict__ Whh,
                                              const float* __restrict__ bih,
                                              const float* __restrict__ bhh) {
    __shared__ float sx[64 * 64];
    __shared__ float sW[48 * 128];
    int t  = threadIdx.x;
    int g0 = blockIdx.x * 64;
    int k  = t & 31;
    int rg = t >> 5;

    for (int i = t; i < 64 * 64; i += 256) {
        int g = i >> 6, c = i & 63;
        int gg = g0 + g;
        float v = 0.0f;
        if (gg < NG) v = (c < 32) ? g_sh[gg * 32 + c] : g_rr[gg * 32 + (c - 32)];
        sx[i] = v;
    }

    float acc[8][4];
    #pragma unroll
    for (int r = 0; r < 8; r++)
        #pragma unroll
        for (int j = 0; j < 4; j++) acc[r][j] = 0.0f;

    #pragma unroll 1
    for (int kc = 0; kc < 2; kc++) {
        __syncthreads();
        for (int i = t; i < 48 * 128; i += 256) {
            int c  = kc * 48 + (i >> 7);
            int kk = i & 127;
            sW[i] = (c < 64) ? Wih[kk * 64 + c] : Whh[kk * 32 + (c - 64)];
        }
        __syncthreads();
        for (int cc = 0; cc < 48; cc++) {
            int c  = kc * 48 + cc;
            int cx = (c < 64) ? c : (c - 64);
            float b0 = sW[cc * 128 + k];
            float b1 = sW[cc * 128 + 32 + k];
            float b2v = sW[cc * 128 + 64 + k];
            float b3 = sW[cc * 128 + 96 + k];
            #pragma unroll
            for (int r = 0; r < 8; r++) {
                float a = sx[(rg * 8 + r) * 64 + cx];
                acc[r][0] += a * b0;
                acc[r][1] += a * b1;
                acc[r][2] += a * b2v;
                acc[r][3] += a * b3;
            }
        }
    }

    float bi0 = __ldg(&bih[k])      + __ldg(&bhh[k]);
    float bf  = __ldg(&bih[32 + k]) + __ldg(&bhh[32 + k]);
    float bg  = __ldg(&bih[64 + k]) + __ldg(&bhh[64 + k]);
    float bo  = __ldg(&bih[96 + k]) + __ldg(&bhh[96 + k]);
    #pragma unroll
    for (int r = 0; r < 8; r++) {
        int gg = g0 + rg * 8 + r;
        if (gg >= NG) break;
        float i_ = sigm(acc[r][0] + bi0);
        float f_ = sigm(acc[r][1] + bf);
        float gv = tanhf(acc[r][2] + bg);
        float o_ = sigm(acc[r][3] + bo);
        float cn = f_ * g_sc[gg * 32 + k] + i_ * gv;
        g_sc[gg * 32 + k] = cn;
        g_sh[gg * 32 + k] = o_ * tanhf(cn);
    }
}

// ---------------- output head ----------------
__global__ void k_output(const float* __restrict__ W1, const float* __restrict__ b1,
                         const float* __restrict__ W2, const float* __restrict__ b2,
                         float* __restrict__ out) {
    int g = blockIdx.x * blockDim.x + threadIdx.x;
    if (g >= NG) return;
    float emb[64];
    #pragma unroll
    for (int c = 0; c < 32; c++) {
        emb[c]      = g_sh[g * 32 + c];
        emb[32 + c] = g_rr[g * 32 + c];
    }
    float hid[32];
    #pragma unroll
    for (int c = 0; c < 32; c++) {
        float acc = __ldg(&b1[c]);
        #pragma unroll
        for (int d = 0; d < 64; d++) acc += emb[d] * __ldg(&W1[d * 32 + c]);
        hid[c] = fmaxf(acc, 0.0f);
    }
    #pragma unroll
    for (int kk = 0; kk < 3; kk++) {
        float acc = __ldg(&b2[kk]);
        #pragma unroll
        for (int c = 0; c < 32; c++) acc += hid[c] * __ldg(&W2[c * 3 + kk]);
        out[g * 3 + kk] = acc;
    }
}

// ---------------- launch ----------------
extern "C" void kernel_launch(void* const* d_in, const int* in_sizes, int n_in,
                              void* d_out, int out_size) {
    const float* nf     = (const float*)d_in[0];
    const float* ef     = (const float*)d_in[1];
    const float* enc_W  = (const float*)d_in[2];
    const float* enc_b  = (const float*)d_in[3];
    const float* e_W1   = (const float*)d_in[4];
    const float* e_b1   = (const float*)d_in[5];
    const float* e_W2   = (const float*)d_in[6];
    const float* e_b2   = (const float*)d_in[7];
    const float* gWih   = (const float*)d_in[8];
    const float* gWhh   = (const float*)d_in[9];
    const float* gbih   = (const float*)d_in[10];
    const float* gbhh   = (const float*)d_in[11];
    const float* lWih   = (const float*)d_in[12];
    const float* lWhh   = (const float*)d_in[13];
    const float* lbih   = (const float*)d_in[14];
    const float* lbhh   = (const float*)d_in[15];
    const float* oW1    = (const float*)d_in[16];
    const float* ob1    = (const float*)d_in[17];
    const float* oW2    = (const float*)d_in[18];
    const float* ob2    = (const float*)d_in[19];
    const int*   eidx   = (const int*)d_in[20];
    const int*   batch  = (const int*)d_in[21];
    float* out = (float*)d_out;

    cudaFuncSetAttribute(k_msg_fused, cudaFuncAttributeMaxDynamicSharedMemorySize,
                         MSG_SMEM);

    // order chosen so the 4th launch (ncu capture target) is k_msg_fused
    k_packW2<<<(64 * 1024 + 255) / 256, 256>>>(e_W2);
    k_encode<<<(N_NODES + 255) / 256, 256>>>(nf, enc_W, enc_b);
    k_edgehid<<<(N_EDGES + 255) / 256, 256>>>(ef, e_W1, e_b1);

    for (int r = 0; r < 3; r++) {
        k_msg_fused<<<(N_EDGES + 127) / 128, 256, MSG_SMEM>>>(eidx, e_b2);
        k_gru<<<(N_NODES + 255) / 256, 256>>>(gWih, gWhh, gbih, gbhh);
    }

    k_zero_s2s<<<(NG * H + 255) / 256, 256>>>();
    k_offs<<<(N_NODES + 255) / 256, 256>>>(batch);

    for (int s = 0; s < 4; s++) {
        k_attend<<<(NG * 32 + 255) / 256, 256>>>();
        k_lstm<<<(NG + 63) / 64, 256>>>(lWih, lWhh, lbih, lbhh);
    }

    k_output<<<(NG + 255) / 256, 256>>>(oW1, ob1, oW2, ob2, out);
}

// round 11
// speedup vs baseline: 1.1359x; 1.0172x over previous
#include <cuda_runtime.h>
#include <cuda_fp16.h>
#include <math_constants.h>

#define N_NODES 100000
#define N_EDGES 200000
#define NG      2000
#define H       32

typedef unsigned long long ull;

// ---------------- device scratch (alloc-free) ----------------
__device__ float  g_h[N_NODES * H];                 // node hidden fp32  12.8 MB
__device__ __half g_hh[N_NODES * H];                // node hidden fp16   6.4 MB
__device__ float  g_m[N_NODES * H];                 // aggregated msgs   12.8 MB
__device__ __half g_rh[(size_t)N_EDGES * 64];       // edge hidden fp16  25.6 MB
__device__ __half g_W2h[1024 * 64];                 // W2 fp16 transposed [n][k], 128 KB
__device__ float  g_sh[NG * H];                     // set2set h
__device__ float  g_sc[NG * H];                     // set2set c
__device__ float  g_rr[NG * H];                     // readout r
__device__ int    g_offs[NG + 1];                   // graph segment offsets

// ---------------- helpers ----------------
__device__ __forceinline__ ull pk2(float x) {
    ull r; asm("mov.b64 %0, {%1, %1};" : "=l"(r) : "f"(x)); return r;
}
__device__ __forceinline__ ull pkab(float lo, float hi) {
    ull r; asm("mov.b64 %0, {%1, %2};" : "=l"(r) : "f"(lo), "f"(hi)); return r;
}
__device__ __forceinline__ ull fma2(ull a, ull b, ull c) {
    ull d; asm("fma.rn.f32x2 %0, %1, %2, %3;" : "=l"(d) : "l"(a), "l"(b), "l"(c)); return d;
}
__device__ __forceinline__ void unpk2(ull v, float& lo, float& hi) {
    asm("mov.b64 {%0, %1}, %2;" : "=f"(lo), "=f"(hi) : "l"(v));
}
__device__ __forceinline__ void cpa16(void* dst, const void* src) {
    unsigned d = (unsigned)__cvta_generic_to_shared(dst);
    asm volatile("cp.async.cg.shared.global [%0], [%1], 16;" :: "r"(d), "l"(src));
}
__device__ __forceinline__ float warpMax(float v) {
    #pragma unroll
    for (int o = 16; o > 0; o >>= 1) v = fmaxf(v, __shfl_xor_sync(0xffffffffu, v, o));
    return v;
}
__device__ __forceinline__ float warpSum(float v) {
    #pragma unroll
    for (int o = 16; o > 0; o >>= 1) v += __shfl_xor_sync(0xffffffffu, v, o);
    return v;
}
__device__ __forceinline__ float sigm(float x) { return 1.0f / (1.0f + expf(-x)); }

// ---------------- zero (set2set state only) ----------------
__global__ void k_zero_s2s() {
    int i = blockIdx.x * blockDim.x + threadIdx.x;
    if (i < NG * H) { g_sh[i] = 0.0f; g_sc[i] = 0.0f; g_rr[i] = 0.0f; }
}

// ---------------- W2 pack: g_W2h[n][k] = fp16(W2[k][n]) ----------------
__global__ void k_packW2(const float* __restrict__ W2) {
    int i = blockIdx.x * blockDim.x + threadIdx.x;
    if (i >= 64 * 1024) return;
    int k = i >> 10, n = i & 1023;
    g_W2h[n * 64 + k] = __float2half_rn(W2[i]);
}

// ---------------- encoder: h = nf @ enc_W + enc_b; writes fp16 mirror; zeros m
__global__ void k_encode(const float* __restrict__ nf, const float* __restrict__ W,
                         const float* __restrict__ b) {
    __shared__ float sW[16 * 32];
    __shared__ float sb[32];
    int t = threadIdx.x;
    for (int i = t; i < 512; i += 256) sW[i] = W[i];
    if (t < 32) sb[t] = b[t];
    __syncthreads();
    int n = blockIdx.x * blockDim.x + t;
    if (n >= N_NODES) return;
    float x[16];
    const float4* p = (const float4*)(nf + (long long)n * 16);
    #pragma unroll
    for (int q = 0; q < 4; q++) {
        float4 v = p[q];
        x[q*4+0] = v.x; x[q*4+1] = v.y; x[q*4+2] = v.z; x[q*4+3] = v.w;
    }
    float hv[32];
    #pragma unroll
    for (int c = 0; c < 32; c++) {
        float acc = sb[c];
        #pragma unroll
        for (int d = 0; d < 16; d++) acc += x[d] * sW[d * 32 + c];
        hv[c] = acc;
    }
    float4* hp = (float4*)&g_h[n * 32];
    float4* mz = (float4*)&g_m[n * 32];
    __half2* hh = (__half2*)&g_hh[n * 32];
    #pragma unroll
    for (int q = 0; q < 8; q++) {
        hp[q] = make_float4(hv[q*4], hv[q*4+1], hv[q*4+2], hv[q*4+3]);
        mz[q] = make_float4(0.f, 0.f, 0.f, 0.f);
    }
    #pragma unroll
    for (int c2 = 0; c2 < 16; c2++)
        hh[c2] = __floats2half2_rn(hv[2*c2], hv[2*c2+1]);
}

// ---------------- edge hidden: rh = fp16(relu(ef @ e_W1 + e_b1)) ----------------
__global__ void k_edgehid(const float* __restrict__ ef, const float* __restrict__ W,
                          const float* __restrict__ b) {
    __shared__ float sW[8 * 64];
    __shared__ float sb[64];
    int t = threadIdx.x;
    for (int i = t; i < 512; i += 256) sW[i] = W[i];
    if (t < 64) sb[t] = b[t];
    __syncthreads();
    int e = blockIdx.x * blockDim.x + t;
    if (e >= N_EDGES) return;
    float x[8];
    const float4* p = (const float4*)(ef + (long long)e * 8);
    float4 v0 = p[0], v1 = p[1];
    x[0]=v0.x; x[1]=v0.y; x[2]=v0.z; x[3]=v0.w;
    x[4]=v1.x; x[5]=v1.y; x[6]=v1.z; x[7]=v1.w;
    float o[64];
    #pragma unroll
    for (int c = 0; c < 64; c++) {
        float acc = sb[c];
        #pragma unroll
        for (int d = 0; d < 8; d++) acc += x[d] * sW[d * 64 + c];
        o[c] = fmaxf(acc, 0.0f);
    }
    __half2* dst = (__half2*)&g_rh[(size_t)e * 64];
    #pragma unroll
    for (int c2 = 0; c2 < 32; c2++)
        dst[c2] = __floats2half2_rn(o[2 * c2], o[2 * c2 + 1]);
}

// ---------------- FUSED message pass: m[tgt] += (rh[e] @ W2 + b2) @ h[src] ------
// Per block: 128 edges. A computed per 128-col chunk via HMMA, consumed from
// registers. Wt is DOUBLE-BUFFERED via cp.async: chunk c+1 prefetched during
// chunk c compute -> 9 barriers instead of 16, L2 latency hidden, no reg cost.
// Scatter: staged in sMsg, then line-coalesced atomics.
// smem (87040 B): Rs 18432 | Wt0 18432 | Wt1 18432 | Hs 10240 | sMsg 16896 |
//                 sTgt 512 | b2s 4096
#define ROWP 72
#define HSTR 40
#define MSG_SMEM 87040
__global__ void __launch_bounds__(256, 2) k_msg_fused(const int* __restrict__ ei,
                                                      const float* __restrict__ b2) {
    extern __shared__ unsigned char dsm[];
    __half* Rs   = (__half*)dsm;                       // [128][ROWP]
    __half* Wt0  = (__half*)(dsm + 18432);             // [128][ROWP]
    __half* Wt1  = (__half*)(dsm + 36864);             // [128][ROWP]
    __half* Hs   = (__half*)(dsm + 55296);             // [128][HSTR]
    float*  sMsg = (float*)(dsm + 65536);              // [128][33]
    int*    sTgt = (int*)(dsm + 82432);                // [128]
    float*  b2s  = (float*)(dsm + 82944);              // [1024]

    int t    = threadIdx.x;
    int lane = t & 31;
    int wid  = t >> 5;
    int e0   = blockIdx.x * 128;

    // prefetch Wt chunk 0 via cp.async (1024 granules of 16B, 4/thread)
    #pragma unroll
    for (int i = 0; i < 4; i++) {
        int g   = t + 256 * i;
        int row = g >> 3;
        int kg  = g & 7;
        cpa16(&Wt0[row * ROWP + kg * 8], &g_W2h[(size_t)row * 64 + kg * 8]);
    }
    asm volatile("cp.async.commit_group;");

    // load rh tile [128 x 64] fp16
    #pragma unroll
    for (int i = 0; i < 4; i++) {
        int g   = t + 256 * i;
        int row = g >> 3;
        int kg  = g & 7;
        uint4 v = make_uint4(0u, 0u, 0u, 0u);
        int e = e0 + row;
        if (e < N_EDGES) v = *(const uint4*)&g_rh[(size_t)e * 64 + kg * 8];
        *(uint4*)&Rs[row * ROWP + kg * 8] = v;
    }
    // gather h[src] fp16 -> Hs; load tgt
    {
        int row = t >> 1, hf = t & 1;
        int e = e0 + row;
        bool ok = e < N_EDGES;
        int src = 0;
        if (ok) {
            src = ei[e];
            if (hf == 0) sTgt[row] = ei[N_EDGES + e];
        }
        const uint4* hp = (const uint4*)&g_hh[src * 32 + hf * 16];
        #pragma unroll
        for (int qq = 0; qq < 2; qq++) {
            uint4 v = ok ? hp[qq] : make_uint4(0u, 0u, 0u, 0u);
            *(uint4*)&Hs[row * HSTR + hf * 16 + qq * 8] = v;
        }
    }
    // full bias vector once (1024 floats)
    ((float4*)b2s)[t] = ((const float4*)b2)[t];

    asm volatile("cp.async.wait_group 0;");
    __syncthreads();

    int warpM = (wid & 1) * 64;
    int warpN = (wid >> 1) * 32;
    int aRow  = warpM + (lane & 15);
    int aColB = (lane >> 4) << 3;
    int bRow  = warpN + (lane & 7) + ((lane >> 4) << 3);
    int bColB = ((lane >> 3) & 1) << 3;

    #pragma unroll 1
    for (int c = 0; c < 8; c++) {
        const __half* Wtc = (c & 1) ? Wt1 : Wt0;
        // prefetch next chunk into the alternate buffer (safe: it was last read
        // in chunk c-1, and the barrier at end of c-1 ordered those reads)
        if (c < 7) {
            __half* Wtn = (c & 1) ? Wt0 : Wt1;
            #pragma unroll
            for (int i = 0; i < 4; i++) {
                int g   = t + 256 * i;
                int row = g >> 3;
                int kg  = g & 7;
                cpa16(&Wtn[row * ROWP + kg * 8],
                      &g_W2h[(size_t)((c + 1) * 128 + row) * 64 + kg * 8]);
            }
            asm volatile("cp.async.commit_group;");
        }

        float acc[4][4][4];
        #pragma unroll
        for (int mt = 0; mt < 4; mt++)
            #pragma unroll
            for (int nt = 0; nt < 4; nt++)
                #pragma unroll
                for (int q = 0; q < 4; q++) acc[mt][nt][q] = 0.0f;

        #pragma unroll
        for (int ks = 0; ks < 4; ks++) {
            int k0 = ks * 16;
            unsigned a[4][4];
            #pragma unroll
            for (int mt = 0; mt < 4; mt++) {
                unsigned addr = (unsigned)__cvta_generic_to_shared(
                    &Rs[(aRow + mt * 16) * ROWP + k0 + aColB]);
                asm volatile("ldmatrix.sync.aligned.m8n8.x4.shared.b16 {%0,%1,%2,%3}, [%4];"
                             : "=r"(a[mt][0]), "=r"(a[mt][1]), "=r"(a[mt][2]), "=r"(a[mt][3])
                             : "r"(addr));
            }
            unsigned bf[4][2];
            #pragma unroll
            for (int p = 0; p < 2; p++) {
                unsigned addr = (unsigned)__cvta_generic_to_shared(
                    &Wtc[(bRow + p * 16) * ROWP + k0 + bColB]);
                asm volatile("ldmatrix.sync.aligned.m8n8.x4.shared.b16 {%0,%1,%2,%3}, [%4];"
                             : "=r"(bf[2*p][0]), "=r"(bf[2*p][1]),
                               "=r"(bf[2*p+1][0]), "=r"(bf[2*p+1][1])
                             : "r"(addr));
            }
            #pragma unroll
            for (int mt = 0; mt < 4; mt++)
                #pragma unroll
                for (int nt = 0; nt < 4; nt++) {
                    asm volatile(
                        "mma.sync.aligned.m16n8k16.row.col.f32.f16.f16.f32 "
                        "{%0,%1,%2,%3}, {%4,%5,%6,%7}, {%8,%9}, {%0,%1,%2,%3};"
                        : "+f"(acc[mt][nt][0]), "+f"(acc[mt][nt][1]),
                          "+f"(acc[mt][nt][2]), "+f"(acc[mt][nt][3])
                        : "r"(a[mt][0]), "r"(a[mt][1]), "r"(a[mt][2]), "r"(a[mt][3]),
                          "r"(bf[nt][0]), "r"(bf[nt][1]));
                }
        }

        // bias
        #pragma unroll
        for (int nt = 0; nt < 4; nt++) {
            float2 bb = *(const float2*)&b2s[c * 128 + warpN + nt * 8 + (lane & 3) * 2];
            #pragma unroll
            for (int mt = 0; mt < 4; mt++) {
                acc[mt][nt][0] += bb.x; acc[mt][nt][1] += bb.y;
                acc[mt][nt][2] += bb.x; acc[mt][nt][3] += bb.y;
            }
        }

        // matvec over j within the warp; stage result in sMsg (no atomics)
        int i_out = 4 * c + (wid >> 1);
        const __half2* Hs2 = (const __half2*)Hs;
        #pragma unroll
        for (int mt = 0; mt < 4; mt++) {
            #pragma unroll
            for (int qh = 0; qh < 2; qh++) {
                int rowl = warpM + mt * 16 + (lane >> 2) + 8 * qh;
                float partial = 0.0f;
                #pragma unroll
                for (int nt = 0; nt < 4; nt++) {
                    float2 hf2 = __half22float2(Hs2[rowl * (HSTR/2) + nt * 4 + (lane & 3)]);
                    partial += acc[mt][nt][2 * qh + 0] * hf2.x;
                    partial += acc[mt][nt][2 * qh + 1] * hf2.y;
                }
                partial += __shfl_xor_sync(0xffffffffu, partial, 1);
                partial += __shfl_xor_sync(0xffffffffu, partial, 2);
                if ((lane & 3) == 0)
                    sMsg[rowl * 33 + i_out] = partial;
            }
        }

        asm volatile("cp.async.wait_group 0;");
        __syncthreads();
    }

    // coalesced flush: warp <-> edge, lanes <-> 32 consecutive g_m floats
    #pragma unroll 1
    for (int idx = t; idx < 128 * 32; idx += 256) {
        int e = idx >> 5, i = idx & 31;
        if (e0 + e < N_EDGES)
            atomicAdd(&g_m[sTgt[e] * 32 + i], sMsg[e * 33 + i]);
    }
}

// ---------------- GRU cell (f32x2 k-pairs); writes fp16 mirror; re-zeros m ----
__global__ void __launch_bounds__(256) k_gru(const float* __restrict__ Wih,
                                             const float* __restrict__ Whh,
                                             const float* __restrict__ bih,
                                             const float* __restrict__ bhh) {
    __shared__ ull sWi2[3 * 16 * 32];
    __shared__ ull sWh2[3 * 16 * 32];
    __shared__ float sbi[96];
    __shared__ float sbh[96];
    int t = threadIdx.x;
    for (int i = t; i < 1536; i += 256) {
        int g  = i >> 9;
        int k2 = (i >> 5) & 15;
        int c  = i & 31;
        int k  = g * 32 + 2 * k2;
        sWi2[i] = pkab(Wih[k * 32 + c], Wih[(k + 1) * 32 + c]);
        sWh2[i] = pkab(Whh[k * 32 + c], Whh[(k + 1) * 32 + c]);
    }
    if (t < 96) { sbi[t] = bih[t]; sbh[t] = bhh[t]; }
    __syncthreads();
    int n = blockIdx.x * blockDim.x + t;
    if (n >= N_NODES) return;

    float mv[32], hv[32];
    const float4* mp = (const float4*)&g_m[n * 32];
    const float4* hp = (const float4*)&g_h[n * 32];
    #pragma unroll
    for (int q = 0; q < 8; q++) {
        float4 a = mp[q]; mv[q*4]=a.x; mv[q*4+1]=a.y; mv[q*4+2]=a.z; mv[q*4+3]=a.w;
        float4 b = hp[q]; hv[q*4]=b.x; hv[q*4+1]=b.y; hv[q*4+2]=b.z; hv[q*4+3]=b.w;
    }
    float4* mz = (float4*)&g_m[n * 32];
    #pragma unroll
    for (int q = 0; q < 8; q++) mz[q] = make_float4(0.f, 0.f, 0.f, 0.f);

    #pragma unroll 1
    for (int k2 = 0; k2 < 16; k2++) {
        int k = 2 * k2;
        ull accr = pkab(sbi[k] + sbh[k], sbi[k + 1] + sbh[k + 1]);
        ull accz = pkab(sbi[32 + k] + sbh[32 + k], sbi[33 + k] + sbh[33 + k]);
        ull accn = pkab(sbi[64 + k], sbi[65 + k]);
        ull acch = pkab(sbh[64 + k], sbh[65 + k]);
        const ull* wir = &sWi2[(0 * 16 + k2) * 32];
        const ull* wiz = &sWi2[(1 * 16 + k2) * 32];
        const ull* win = &sWi2[(2 * 16 + k2) * 32];
        const ull* whr = &sWh2[(0 * 16 + k2) * 32];
        const ull* whz = &sWh2[(1 * 16 + k2) * 32];
        const ull* whn = &sWh2[(2 * 16 + k2) * 32];
        #pragma unroll
        for (int c = 0; c < 32; c++) {
            ull pm = pk2(mv[c]);
            ull ph = pk2(hv[c]);
            accr = fma2(pm, wir[c], accr);
            accr = fma2(ph, whr[c], accr);
            accz = fma2(pm, wiz[c], accz);
            accz = fma2(ph, whz[c], accz);
            accn = fma2(pm, win[c], accn);
            acch = fma2(ph, whn[c], acch);
        }
        float rlo, rhi, zlo, zhi, nlo, nhi, hlo, hhi;
        unpk2(accr, rlo, rhi);
        unpk2(accz, zlo, zhi);
        unpk2(accn, nlo, nhi);
        unpk2(acch, hlo, hhi);
        float r0 = sigm(rlo), z0 = sigm(zlo);
        float n0 = tanhf(nlo + r0 * hlo);
        float r1 = sigm(rhi), z1 = sigm(zhi);
        float n1 = tanhf(nhi + r1 * hhi);
        float2 hnew;
        hnew.x = (1.0f - z0) * n0 + z0 * hv[k];
        hnew.y = (1.0f - z1) * n1 + z1 * hv[k + 1];
        *(float2*)&g_h[n * 32 + k] = hnew;
        *(__half2*)&g_hh[n * 32 + k] = __floats2half2_rn(hnew.x, hnew.y);
    }
}

// ---------------- graph segment offsets (batch_indices sorted) ----------------
__global__ void k_offs(const int* __restrict__ batch) {
    int n = blockIdx.x * blockDim.x + threadIdx.x;
    if (n >= N_NODES) return;
    int b = batch[n];
    int prev = (n == 0) ? -1 : batch[n - 1];
    for (int g = prev + 1; g <= b; g++) g_offs[g] = n;
    if (n == N_NODES - 1)
        for (int g = b + 1; g <= NG; g++) g_offs[g] = N_NODES;
}

// ---------------- Set2Set attention + readout (online softmax, warp/graph) ----
__global__ void __launch_bounds__(256) k_attend() {
    int lane = threadIdx.x & 31;
    int g = (blockIdx.x * blockDim.x + threadIdx.x) >> 5;
    if (g >= NG) return;
    int s = g_offs[g], tEnd = g_offs[g + 1];
    float q = g_sh[g * 32 + lane];
    float maxv = -CUDART_INF_F, denom = 0.0f, racc = 0.0f;

    for (int base = s; base < tEnd; base += 32) {
        int n = base + lane;
        bool act = n < tEnd;
        int nn = act ? n : s;
        float rv[32];
        const float4* hp4 = (const float4*)&g_h[nn * 32];
        #pragma unroll
        for (int q4 = 0; q4 < 8; q4++) {
            float4 v = hp4[q4];
            rv[q4*4] = v.x; rv[q4*4+1] = v.y; rv[q4*4+2] = v.z; rv[q4*4+3] = v.w;
        }
        float ev = 0.0f;
        #pragma unroll
        for (int j = 0; j < 32; j++)
            ev += rv[j] * __shfl_sync(0xffffffffu, q, j);
        float e_n = act ? ev : -CUDART_INF_F;
        float cm = warpMax(e_n);
        float nm = fmaxf(maxv, cm);
        float scale = (maxv == -CUDART_INF_F) ? 0.0f : expf(maxv - nm);
        float p = act ? expf(e_n - nm) : 0.0f;
        float ps = warpSum(p);
        denom = denom * scale + ps;
        racc *= scale;
        maxv = nm;
        int cnt = min(32, tEnd - base);
        for (int n2 = 0; n2 < cnt; n2++) {
            float pn = __shfl_sync(0xffffffffu, p, n2);
            racc += pn * g_h[(base + n2) * 32 + lane];
        }
    }
    g_rr[g * 32 + lane] = (denom > 0.0f) ? (racc / denom) : 0.0f;
}

// ---------------- Set2Set LSTM step (fused mini-GEMM, 64 graphs/block) --------
__global__ void __launch_bounds__(256) k_lstm(const float* __restrict__ Wih,
                                              const float* __restrict__ Whh,
                                              const float* __restrict__ bih,
                                              const float* __restrict__ bhh) {
    __shared__ float sx[64 * 64];
    __shared__ float sW[48 * 128];
    int t  = threadIdx.x;
    int g0 = blockIdx.x * 64;
    int k  = t & 31;
    int rg = t >> 5;

    for (int i = t; i < 64 * 64; i += 256) {
        int g = i >> 6, c = i & 63;
        int gg = g0 + g;
        float v = 0.0f;
        if (gg < NG) v = (c < 32) ? g_sh[gg * 32 + c] : g_rr[gg * 32 + (c - 32)];
        sx[i] = v;
    }

    float acc[8][4];
    #pragma unroll
    for (int r = 0; r < 8; r++)
        #pragma unroll
        for (int j = 0; j < 4; j++) acc[r][j] = 0.0f;

    #pragma unroll 1
    for (int kc = 0; kc < 2; kc++) {
        __syncthreads();
        for (int i = t; i < 48 * 128; i += 256) {
            int c  = kc * 48 + (i >> 7);
            int kk = i & 127;
            sW[i] = (c < 64) ? Wih[kk * 64 + c] : Whh[kk * 32 + (c - 64)];
        }
        __syncthreads();
        for (int cc = 0; cc < 48; cc++) {
            int c  = kc * 48 + cc;
            int cx = (c < 64) ? c : (c - 64);
            float b0 = sW[cc * 128 + k];
            float b1 = sW[cc * 128 + 32 + k];
            float b2v = sW[cc * 128 + 64 + k];
            float b3 = sW[cc * 128 + 96 + k];
            #pragma unroll
            for (int r = 0; r < 8; r++) {
                float a = sx[(rg * 8 + r) * 64 + cx];
                acc[r][0] += a * b0;
                acc[r][1] += a * b1;
                acc[r][2] += a * b2v;
                acc[r][3] += a * b3;
            }
        }
    }

    float bi0 = __ldg(&bih[k])      + __ldg(&bhh[k]);
    float bf  = __ldg(&bih[32 + k]) + __ldg(&bhh[32 + k]);
    float bg  = __ldg(&bih[64 + k]) + __ldg(&bhh[64 + k]);
    float bo  = __ldg(&bih[96 + k]) + __ldg(&bhh[96 + k]);
    #pragma unroll
    for (int r = 0; r < 8; r++) {
        int gg = g0 + rg * 8 + r;
        if (gg >= NG) break;
        float i_ = sigm(acc[r][0] + bi0);
        float f_ = sigm(acc[r][1] + bf);
        float gv = tanhf(acc[r][2] + bg);
        float o_ = sigm(acc[r][3] + bo);
        float cn = f_ * g_sc[gg * 32 + k] + i_ * gv;
        g_sc[gg * 32 + k] = cn;
        g_sh[gg * 32 + k] = o_ * tanhf(cn);
    }
}

// ---------------- output head ----------------
__global__ void k_output(const float* __restrict__ W1, const float* __restrict__ b1,
                         const float* __restrict__ W2, const float* __restrict__ b2,
                         float* __restrict__ out) {
    int g = blockIdx.x * blockDim.x + threadIdx.x;
    if (g >= NG) return;
    float emb[64];
    #pragma unroll
    for (int c = 0; c < 32; c++) {
        emb[c]      = g_sh[g * 32 + c];
        emb[32 + c] = g_rr[g * 32 + c];
    }
    float hid[32];
    #pragma unroll
    for (int c = 0; c < 32; c++) {
        float acc = __ldg(&b1[c]);
        #pragma unroll
        for (int d = 0; d < 64; d++) acc += emb[d] * __ldg(&W1[d * 32 + c]);
        hid[c] = fmaxf(acc, 0.0f);
    }
    #pragma unroll
    for (int kk = 0; kk < 3; kk++) {
        float acc = __ldg(&b2[kk]);
        #pragma unroll
        for (int c = 0; c < 32; c++) acc += hid[c] * __ldg(&W2[c * 3 + kk]);
        out[g * 3 + kk] = acc;
    }
}

// ---------------- launch ----------------
extern "C" void kernel_launch(void* const* d_in, const int* in_sizes, int n_in,
                              void* d_out, int out_size) {
    const float* nf     = (const float*)d_in[0];
    const float* ef     = (const float*)d_in[1];
    const float* enc_W  = (const float*)d_in[2];
    const float* enc_b  = (const float*)d_in[3];
    const float* e_W1   = (const float*)d_in[4];
    const float* e_b1   = (const float*)d_in[5];
    const float* e_W2   = (const float*)d_in[6];
    const float* e_b2   = (const float*)d_in[7];
    const float* gWih   = (const float*)d_in[8];
    const float* gWhh   = (const float*)d_in[9];
    const float* gbih   = (const float*)d_in[10];
    const float* gbhh   = (const float*)d_in[11];
    const float* lWih   = (const float*)d_in[12];
    const float* lWhh   = (const float*)d_in[13];
    const float* lbih   = (const float*)d_in[14];
    const float* lbhh   = (const float*)d_in[15];
    const float* oW1    = (const float*)d_in[16];
    const float* ob1    = (const float*)d_in[17];
    const float* oW2    = (const float*)d_in[18];
    const float* ob2    = (const float*)d_in[19];
    const int*   eidx   = (const int*)d_in[20];
    const int*   batch  = (const int*)d_in[21];
    float* out = (float*)d_out;

    cudaFuncSetAttribute(k_msg_fused, cudaFuncAttributeMaxDynamicSharedMemorySize,
                         MSG_SMEM);

    // order chosen so the 4th launch (ncu capture target) is k_msg_fused
    k_packW2<<<(64 * 1024 + 255) / 256, 256>>>(e_W2);
    k_encode<<<(N_NODES + 255) / 256, 256>>>(nf, enc_W, enc_b);
    k_edgehid<<<(N_EDGES + 255) / 256, 256>>>(ef, e_W1, e_b1);

    for (int r = 0; r < 3; r++) {
        k_msg_fused<<<(N_EDGES + 127) / 128, 256, MSG_SMEM>>>(eidx, e_b2);
        k_gru<<<(N_NODES + 255) / 256, 256>>>(gWih, gWhh, gbih, gbhh);
    }

    k_zero_s2s<<<(NG * H + 255) / 256, 256>>>();
    k_offs<<<(N_NODES + 255) / 256, 256>>>(batch);

    for (int s = 0; s < 4; s++) {
        k_attend<<<(NG * 32 + 255) / 256, 256>>>();
        k_lstm<<<(NG + 63) / 64, 256>>>(lWih, lWhh, lbih, lbhh);
    }

    k_output<<<(NG + 255) / 256, 256>>>(oW1, ob1, oW2, ob2, out);
}

// round 12
// speedup vs baseline: 1.3104x; 1.1536x over previous
#include <cuda_runtime.h>
#include <cuda_fp16.h>
#include <math_constants.h>

#define N_NODES 100000
#define N_EDGES 200000
#define NG      2000
#define H       32

typedef unsigned long long ull;

// ---------------- device scratch (alloc-free) ----------------
__device__ float  g_h[N_NODES * H];                 // node hidden fp32  12.8 MB
__device__ __half g_hh[N_NODES * H];                // node hidden fp16   6.4 MB
__device__ float  g_m[N_NODES * H];                 // aggregated msgs   12.8 MB
__device__ __half g_rh[(size_t)N_EDGES * 64];       // edge hidden fp16  25.6 MB
__device__ __half g_W2h[1024 * 64];                 // W2 fp16 transposed [n][k], 128 KB
__device__ int    g_offs[NG + 1];                   // graph segment offsets

// ---------------- helpers ----------------
__device__ __forceinline__ ull pk2(float x) {
    ull r; asm("mov.b64 %0, {%1, %1};" : "=l"(r) : "f"(x)); return r;
}
__device__ __forceinline__ ull pkab(float lo, float hi) {
    ull r; asm("mov.b64 %0, {%1, %2};" : "=l"(r) : "f"(lo), "f"(hi)); return r;
}
__device__ __forceinline__ ull fma2(ull a, ull b, ull c) {
    ull d; asm("fma.rn.f32x2 %0, %1, %2, %3;" : "=l"(d) : "l"(a), "l"(b), "l"(c)); return d;
}
__device__ __forceinline__ void unpk2(ull v, float& lo, float& hi) {
    asm("mov.b64 {%0, %1}, %2;" : "=f"(lo), "=f"(hi) : "l"(v));
}
__device__ __forceinline__ void cpa16(void* dst, const void* src) {
    unsigned d = (unsigned)__cvta_generic_to_shared(dst);
    asm volatile("cp.async.cg.shared.global [%0], [%1], 16;" :: "r"(d), "l"(src));
}
__device__ __forceinline__ float warpMax(float v) {
    #pragma unroll
    for (int o = 16; o > 0; o >>= 1) v = fmaxf(v, __shfl_xor_sync(0xffffffffu, v, o));
    return v;
}
__device__ __forceinline__ float warpSum(float v) {
    #pragma unroll
    for (int o = 16; o > 0; o >>= 1) v += __shfl_xor_sync(0xffffffffu, v, o);
    return v;
}
__device__ __forceinline__ float sigm(float x) { return 1.0f / (1.0f + expf(-x)); }

// ---------------- W2 pack: g_W2h[n][k] = fp16(W2[k][n]) ----------------
__global__ void k_packW2(const float* __restrict__ W2) {
    int i = blockIdx.x * blockDim.x + threadIdx.x;
    if (i >= 64 * 1024) return;
    int k = i >> 10, n = i & 1023;
    g_W2h[n * 64 + k] = __float2half_rn(W2[i]);
}

// ---------------- encoder: h = nf @ enc_W + enc_b; writes fp16 mirror; zeros m
__global__ void k_encode(const float* __restrict__ nf, const float* __restrict__ W,
                         const float* __restrict__ b) {
    __shared__ float sW[16 * 32];
    __shared__ float sb[32];
    int t = threadIdx.x;
    for (int i = t; i < 512; i += 256) sW[i] = W[i];
    if (t < 32) sb[t] = b[t];
    __syncthreads();
    int n = blockIdx.x * blockDim.x + t;
    if (n >= N_NODES) return;
    float x[16];
    const float4* p = (const float4*)(nf + (long long)n * 16);
    #pragma unroll
    for (int q = 0; q < 4; q++) {
        float4 v = p[q];
        x[q*4+0] = v.x; x[q*4+1] = v.y; x[q*4+2] = v.z; x[q*4+3] = v.w;
    }
    float hv[32];
    #pragma unroll
    for (int c = 0; c < 32; c++) {
        float acc = sb[c];
        #pragma unroll
        for (int d = 0; d < 16; d++) acc += x[d] * sW[d * 32 + c];
        hv[c] = acc;
    }
    float4* hp = (float4*)&g_h[n * 32];
    float4* mz = (float4*)&g_m[n * 32];
    __half2* hh = (__half2*)&g_hh[n * 32];
    #pragma unroll
    for (int q = 0; q < 8; q++) {
        hp[q] = make_float4(hv[q*4], hv[q*4+1], hv[q*4+2], hv[q*4+3]);
        mz[q] = make_float4(0.f, 0.f, 0.f, 0.f);
    }
    #pragma unroll
    for (int c2 = 0; c2 < 16; c2++)
        hh[c2] = __floats2half2_rn(hv[2*c2], hv[2*c2+1]);
}

// ---------------- edge hidden: rh = fp16(relu(ef @ e_W1 + e_b1)) ----------------
__global__ void k_edgehid(const float* __restrict__ ef, const float* __restrict__ W,
                          const float* __restrict__ b) {
    __shared__ float sW[8 * 64];
    __shared__ float sb[64];
    int t = threadIdx.x;
    for (int i = t; i < 512; i += 256) sW[i] = W[i];
    if (t < 64) sb[t] = b[t];
    __syncthreads();
    int e = blockIdx.x * blockDim.x + t;
    if (e >= N_EDGES) return;
    float x[8];
    const float4* p = (const float4*)(ef + (long long)e * 8);
    float4 v0 = p[0], v1 = p[1];
    x[0]=v0.x; x[1]=v0.y; x[2]=v0.z; x[3]=v0.w;
    x[4]=v1.x; x[5]=v1.y; x[6]=v1.z; x[7]=v1.w;
    float o[64];
    #pragma unroll
    for (int c = 0; c < 64; c++) {
        float acc = sb[c];
        #pragma unroll
        for (int d = 0; d < 8; d++) acc += x[d] * sW[d * 64 + c];
        o[c] = fmaxf(acc, 0.0f);
    }
    __half2* dst = (__half2*)&g_rh[(size_t)e * 64];
    #pragma unroll
    for (int c2 = 0; c2 < 32; c2++)
        dst[c2] = __floats2half2_rn(o[2 * c2], o[2 * c2 + 1]);
}

// ---------------- FUSED message pass: m[tgt] += (rh[e] @ W2 + b2) @ h[src] ------
#define ROWP 72
#define HSTR 40
#define MSG_SMEM 87040
__global__ void __launch_bounds__(256, 2) k_msg_fused(const int* __restrict__ ei,
                                                      const float* __restrict__ b2) {
    extern __shared__ unsigned char dsm[];
    __half* Rs   = (__half*)dsm;                       // [128][ROWP]
    __half* Wt0  = (__half*)(dsm + 18432);             // [128][ROWP]
    __half* Wt1  = (__half*)(dsm + 36864);             // [128][ROWP]
    __half* Hs   = (__half*)(dsm + 55296);             // [128][HSTR]
    float*  sMsg = (float*)(dsm + 65536);              // [128][33]
    int*    sTgt = (int*)(dsm + 82432);                // [128]
    float*  b2s  = (float*)(dsm + 82944);              // [1024]

    int t    = threadIdx.x;
    int lane = t & 31;
    int wid  = t >> 5;
    int e0   = blockIdx.x * 128;

    // prefetch Wt chunk 0 via cp.async
    #pragma unroll
    for (int i = 0; i < 4; i++) {
        int g   = t + 256 * i;
        int row = g >> 3;
        int kg  = g & 7;
        cpa16(&Wt0[row * ROWP + kg * 8], &g_W2h[(size_t)row * 64 + kg * 8]);
    }
    asm volatile("cp.async.commit_group;");

    // load rh tile [128 x 64] fp16
    #pragma unroll
    for (int i = 0; i < 4; i++) {
        int g   = t + 256 * i;
        int row = g >> 3;
        int kg  = g & 7;
        uint4 v = make_uint4(0u, 0u, 0u, 0u);
        int e = e0 + row;
        if (e < N_EDGES) v = *(const uint4*)&g_rh[(size_t)e * 64 + kg * 8];
        *(uint4*)&Rs[row * ROWP + kg * 8] = v;
    }
    // gather h[src] fp16 -> Hs; load tgt
    {
        int row = t >> 1, hf = t & 1;
        int e = e0 + row;
        bool ok = e < N_EDGES;
        int src = 0;
        if (ok) {
            src = ei[e];
            if (hf == 0) sTgt[row] = ei[N_EDGES + e];
        }
        const uint4* hp = (const uint4*)&g_hh[src * 32 + hf * 16];
        #pragma unroll
        for (int qq = 0; qq < 2; qq++) {
            uint4 v = ok ? hp[qq] : make_uint4(0u, 0u, 0u, 0u);
            *(uint4*)&Hs[row * HSTR + hf * 16 + qq * 8] = v;
        }
    }
    // full bias vector once (1024 floats)
    ((float4*)b2s)[t] = ((const float4*)b2)[t];

    asm volatile("cp.async.wait_group 0;");
    __syncthreads();

    int warpM = (wid & 1) * 64;
    int warpN = (wid >> 1) * 32;
    int aRow  = warpM + (lane & 15);
    int aColB = (lane >> 4) << 3;
    int bRow  = warpN + (lane & 7) + ((lane >> 4) << 3);
    int bColB = ((lane >> 3) & 1) << 3;

    #pragma unroll 1
    for (int c = 0; c < 8; c++) {
        const __half* Wtc = (c & 1) ? Wt1 : Wt0;
        if (c < 7) {
            __half* Wtn = (c & 1) ? Wt0 : Wt1;
            #pragma unroll
            for (int i = 0; i < 4; i++) {
                int g   = t + 256 * i;
                int row = g >> 3;
                int kg  = g & 7;
                cpa16(&Wtn[row * ROWP + kg * 8],
                      &g_W2h[(size_t)((c + 1) * 128 + row) * 64 + kg * 8]);
            }
            asm volatile("cp.async.commit_group;");
        }

        float acc[4][4][4];
        #pragma unroll
        for (int mt = 0; mt < 4; mt++)
            #pragma unroll
            for (int nt = 0; nt < 4; nt++)
                #pragma unroll
                for (int q = 0; q < 4; q++) acc[mt][nt][q] = 0.0f;

        #pragma unroll
        for (int ks = 0; ks < 4; ks++) {
            int k0 = ks * 16;
            unsigned a[4][4];
            #pragma unroll
            for (int mt = 0; mt < 4; mt++) {
                unsigned addr = (unsigned)__cvta_generic_to_shared(
                    &Rs[(aRow + mt * 16) * ROWP + k0 + aColB]);
                asm volatile("ldmatrix.sync.aligned.m8n8.x4.shared.b16 {%0,%1,%2,%3}, [%4];"
                             : "=r"(a[mt][0]), "=r"(a[mt][1]), "=r"(a[mt][2]), "=r"(a[mt][3])
                             : "r"(addr));
            }
            unsigned bf[4][2];
            #pragma unroll
            for (int p = 0; p < 2; p++) {
                unsigned addr = (unsigned)__cvta_generic_to_shared(
                    &Wtc[(bRow + p * 16) * ROWP + k0 + bColB]);
                asm volatile("ldmatrix.sync.aligned.m8n8.x4.shared.b16 {%0,%1,%2,%3}, [%4];"
                             : "=r"(bf[2*p][0]), "=r"(bf[2*p][1]),
                               "=r"(bf[2*p+1][0]), "=r"(bf[2*p+1][1])
                             : "r"(addr));
            }
            #pragma unroll
            for (int mt = 0; mt < 4; mt++)
                #pragma unroll
                for (int nt = 0; nt < 4; nt++) {
                    asm volatile(
                        "mma.sync.aligned.m16n8k16.row.col.f32.f16.f16.f32 "
                        "{%0,%1,%2,%3}, {%4,%5,%6,%7}, {%8,%9}, {%0,%1,%2,%3};"
                        : "+f"(acc[mt][nt][0]), "+f"(acc[mt][nt][1]),
                          "+f"(acc[mt][nt][2]), "+f"(acc[mt][nt][3])
                        : "r"(a[mt][0]), "r"(a[mt][1]), "r"(a[mt][2]), "r"(a[mt][3]),
                          "r"(bf[nt][0]), "r"(bf[nt][1]));
                }
        }

        // bias
        #pragma unroll
        for (int nt = 0; nt < 4; nt++) {
            float2 bb = *(const float2*)&b2s[c * 128 + warpN + nt * 8 + (lane & 3) * 2];
            #pragma unroll
            for (int mt = 0; mt < 4; mt++) {
                acc[mt][nt][0] += bb.x; acc[mt][nt][1] += bb.y;
                acc[mt][nt][2] += bb.x; acc[mt][nt][3] += bb.y;
            }
        }

        // matvec over j within the warp; stage result in sMsg (no atomics)
        int i_out = 4 * c + (wid >> 1);
        const __half2* Hs2 = (const __half2*)Hs;
        #pragma unroll
        for (int mt = 0; mt < 4; mt++) {
            #pragma unroll
            for (int qh = 0; qh < 2; qh++) {
                int rowl = warpM + mt * 16 + (lane >> 2) + 8 * qh;
                float partial = 0.0f;
                #pragma unroll
                for (int nt = 0; nt < 4; nt++) {
                    float2 hf2 = __half22float2(Hs2[rowl * (HSTR/2) + nt * 4 + (lane & 3)]);
                    partial += acc[mt][nt][2 * qh + 0] * hf2.x;
                    partial += acc[mt][nt][2 * qh + 1] * hf2.y;
                }
                partial += __shfl_xor_sync(0xffffffffu, partial, 1);
                partial += __shfl_xor_sync(0xffffffffu, partial, 2);
                if ((lane & 3) == 0)
                    sMsg[rowl * 33 + i_out] = partial;
            }
        }

        asm volatile("cp.async.wait_group 0;");
        __syncthreads();
    }

    // coalesced flush: warp <-> edge, lanes <-> 32 consecutive g_m floats
    #pragma unroll 1
    for (int idx = t; idx < 128 * 32; idx += 256) {
        int e = idx >> 5, i = idx & 31;
        if (e0 + e < N_EDGES)
            atomicAdd(&g_m[sTgt[e] * 32 + i], sMsg[e * 33 + i]);
    }
}

// ---------------- GRU cell (f32x2 k-pairs); writes fp16 mirror; re-zeros m ----
__global__ void __launch_bounds__(256) k_gru(const float* __restrict__ Wih,
                                             const float* __restrict__ Whh,
                                             const float* __restrict__ bih,
                                             const float* __restrict__ bhh) {
    __shared__ ull sWi2[3 * 16 * 32];
    __shared__ ull sWh2[3 * 16 * 32];
    __shared__ float sbi[96];
    __shared__ float sbh[96];
    int t = threadIdx.x;
    for (int i = t; i < 1536; i += 256) {
        int g  = i >> 9;
        int k2 = (i >> 5) & 15;
        int c  = i & 31;
        int k  = g * 32 + 2 * k2;
        sWi2[i] = pkab(Wih[k * 32 + c], Wih[(k + 1) * 32 + c]);
        sWh2[i] = pkab(Whh[k * 32 + c], Whh[(k + 1) * 32 + c]);
    }
    if (t < 96) { sbi[t] = bih[t]; sbh[t] = bhh[t]; }
    __syncthreads();
    int n = blockIdx.x * blockDim.x + t;
    if (n >= N_NODES) return;

    float mv[32], hv[32];
    const float4* mp = (const float4*)&g_m[n * 32];
    const float4* hp = (const float4*)&g_h[n * 32];
    #pragma unroll
    for (int q = 0; q < 8; q++) {
        float4 a = mp[q]; mv[q*4]=a.x; mv[q*4+1]=a.y; mv[q*4+2]=a.z; mv[q*4+3]=a.w;
        float4 b = hp[q]; hv[q*4]=b.x; hv[q*4+1]=b.y; hv[q*4+2]=b.z; hv[q*4+3]=b.w;
    }
    float4* mz = (float4*)&g_m[n * 32];
    #pragma unroll
    for (int q = 0; q < 8; q++) mz[q] = make_float4(0.f, 0.f, 0.f, 0.f);

    #pragma unroll 1
    for (int k2 = 0; k2 < 16; k2++) {
        int k = 2 * k2;
        ull accr = pkab(sbi[k] + sbh[k], sbi[k + 1] + sbh[k + 1]);
        ull accz = pkab(sbi[32 + k] + sbh[32 + k], sbi[33 + k] + sbh[33 + k]);
        ull accn = pkab(sbi[64 + k], sbi[65 + k]);
        ull acch = pkab(sbh[64 + k], sbh[65 + k]);
        const ull* wir = &sWi2[(0 * 16 + k2) * 32];
        const ull* wiz = &sWi2[(1 * 16 + k2) * 32];
        const ull* win = &sWi2[(2 * 16 + k2) * 32];
        const ull* whr = &sWh2[(0 * 16 + k2) * 32];
        const ull* whz = &sWh2[(1 * 16 + k2) * 32];
        const ull* whn = &sWh2[(2 * 16 + k2) * 32];
        #pragma unroll
        for (int c = 0; c < 32; c++) {
            ull pm = pk2(mv[c]);
            ull ph = pk2(hv[c]);
            accr = fma2(pm, wir[c], accr);
            accr = fma2(ph, whr[c], accr);
            accz = fma2(pm, wiz[c], accz);
            accz = fma2(ph, whz[c], accz);
            accn = fma2(pm, win[c], accn);
            acch = fma2(ph, whn[c], acch);
        }
        float rlo, rhi, zlo, zhi, nlo, nhi, hlo, hhi;
        unpk2(accr, rlo, rhi);
        unpk2(accz, zlo, zhi);
        unpk2(accn, nlo, nhi);
        unpk2(acch, hlo, hhi);
        float r0 = sigm(rlo), z0 = sigm(zlo);
        float n0 = tanhf(nlo + r0 * hlo);
        float r1 = sigm(rhi), z1 = sigm(zhi);
        float n1 = tanhf(nhi + r1 * hhi);
        float2 hnew;
        hnew.x = (1.0f - z0) * n0 + z0 * hv[k];
        hnew.y = (1.0f - z1) * n1 + z1 * hv[k + 1];
        *(float2*)&g_h[n * 32 + k] = hnew;
        *(__half2*)&g_hh[n * 32 + k] = __floats2half2_rn(hnew.x, hnew.y);
    }
}

// ---------------- graph segment offsets (batch_indices sorted) ----------------
__global__ void k_offs(const int* __restrict__ batch) {
    int n = blockIdx.x * blockDim.x + threadIdx.x;
    if (n >= N_NODES) return;
    int b = batch[n];
    int prev = (n == 0) ? -1 : batch[n - 1];
    for (int g = prev + 1; g <= b; g++) g_offs[g] = n;
    if (n == N_NODES - 1)
        for (int g = b + 1; g <= NG; g++) g_offs[g] = N_NODES;
}

// ---------------- FUSED Set2Set: 4x(attend+LSTM) + output head, 1 warp/graph --
// State (sh, c, rr) lives in registers (lane = channel). LSTM weights prepacked:
// sWa[k][c] = Wih[k][c] + Whh[k][c] (coeff of sh[c]), sWb[k][c] = Wih[k][32+c]
// (coeff of rr[c]); stride 33 -> bank = (lane+c)%32, conflict-free.
__global__ void __launch_bounds__(256) k_s2s(const float* __restrict__ lWih,
                                             const float* __restrict__ lWhh,
                                             const float* __restrict__ lbih,
                                             const float* __restrict__ lbhh,
                                             const float* __restrict__ oW1,
                                             const float* __restrict__ ob1,
                                             const float* __restrict__ oW2,
                                             const float* __restrict__ ob2,
                                             float* __restrict__ out) {
    __shared__ float sWa[128 * 33];
    __shared__ float sWb[128 * 33];
    __shared__ float sbias[128];
    __shared__ float sW1[64 * 32];
    __shared__ float sW2[96];
    __shared__ float sb1o[32];
    __shared__ float sb2o[3];
    int t = threadIdx.x, lane = t & 31, wid = t >> 5;

    for (int i = t; i < 128 * 32; i += 256) {
        int k = i >> 5, c = i & 31;
        sWa[k * 33 + c] = lWih[k * 64 + c] + lWhh[k * 32 + c];
        sWb[k * 33 + c] = lWih[k * 64 + 32 + c];
    }
    if (t < 128) sbias[t] = lbih[t] + lbhh[t];
    for (int i = t; i < 2048; i += 256) sW1[i] = oW1[i];
    if (t < 96) sW2[t] = oW2[t];
    if (t < 32) sb1o[t] = ob1[t];
    if (t < 3)  sb2o[t] = ob2[t];
    __syncthreads();

    int g = blockIdx.x * 8 + wid;
    if (g >= NG) return;
    int s = g_offs[g], tEnd = g_offs[g + 1];

    float sh = 0.0f, cst = 0.0f, rr = 0.0f;

    #pragma unroll 1
    for (int step = 0; step < 4; step++) {
        // ---- attend (online softmax over this graph's segment) ----
        float q = sh;
        float maxv = -CUDART_INF_F, denom = 0.0f, racc = 0.0f;
        for (int base = s; base < tEnd; base += 32) {
            int n = base + lane;
            bool act = n < tEnd;
            int nn = act ? n : s;
            float rv[32];
            const float4* hp4 = (const float4*)&g_h[nn * 32];
            #pragma unroll
            for (int q4 = 0; q4 < 8; q4++) {
                float4 v = hp4[q4];
                rv[q4*4] = v.x; rv[q4*4+1] = v.y; rv[q4*4+2] = v.z; rv[q4*4+3] = v.w;
            }
            float ev = 0.0f;
            #pragma unroll
            for (int j = 0; j < 32; j++)
                ev += rv[j] * __shfl_sync(0xffffffffu, q, j);
            float e_n = act ? ev : -CUDART_INF_F;
            float cm = warpMax(e_n);
            float nm = fmaxf(maxv, cm);
            float scale = (maxv == -CUDART_INF_F) ? 0.0f : expf(maxv - nm);
            float p = act ? expf(e_n - nm) : 0.0f;
            float ps = warpSum(p);
            denom = denom * scale + ps;
            racc *= scale;
            maxv = nm;
            int cnt = min(32, tEnd - base);
            for (int n2 = 0; n2 < cnt; n2++) {
                float pn = __shfl_sync(0xffffffffu, p, n2);
                racc += pn * g_h[(base + n2) * 32 + lane];
            }
        }
        rr = (denom > 0.0f) ? (racc / denom) : 0.0f;

        // ---- LSTM step (warp matvec, lane computes gates lane, 32+l, 64+l, 96+l)
        float ai = sbias[lane];
        float af = sbias[32 + lane];
        float ag = sbias[64 + lane];
        float ao = sbias[96 + lane];
        #pragma unroll 1
        for (int c = 0; c < 32; c++) {
            float shv = __shfl_sync(0xffffffffu, sh, c);
            float rvv = __shfl_sync(0xffffffffu, rr, c);
            ai += shv * sWa[lane * 33 + c]        + rvv * sWb[lane * 33 + c];
            af += shv * sWa[(32 + lane) * 33 + c] + rvv * sWb[(32 + lane) * 33 + c];
            ag += shv * sWa[(64 + lane) * 33 + c] + rvv * sWb[(64 + lane) * 33 + c];
            ao += shv * sWa[(96 + lane) * 33 + c] + rvv * sWb[(96 + lane) * 33 + c];
        }
        float i_ = sigm(ai), f_ = sigm(af), gv = tanhf(ag), o_ = sigm(ao);
        cst = f_ * cst + i_ * gv;
        sh = o_ * tanhf(cst);
    }

    // ---- output head: hid = relu([sh|rr] @ W1 + b1); out = hid @ W2 + b2 ----
    float hid = sb1o[lane];
    #pragma unroll 1
    for (int d = 0; d < 32; d++) {
        float shv = __shfl_sync(0xffffffffu, sh, d);
        float rvv = __shfl_sync(0xffffffffu, rr, d);
        hid += shv * sW1[d * 32 + lane] + rvv * sW1[(32 + d) * 32 + lane];
    }
    hid = fmaxf(hid, 0.0f);
    float o0 = hid * sW2[lane * 3 + 0];
    float o1 = hid * sW2[lane * 3 + 1];
    float o2 = hid * sW2[lane * 3 + 2];
    o0 = warpSum(o0); o1 = warpSum(o1); o2 = warpSum(o2);
    if (lane == 0) {
        out[g * 3 + 0] = o0 + sb2o[0];
        out[g * 3 + 1] = o1 + sb2o[1];
        out[g * 3 + 2] = o2 + sb2o[2];
    }
}

// ---------------- launch ----------------
extern "C" void kernel_launch(void* const* d_in, const int* in_sizes, int n_in,
                              void* d_out, int out_size) {
    const float* nf     = (const float*)d_in[0];
    const float* ef     = (const float*)d_in[1];
    const float* enc_W  = (const float*)d_in[2];
    const float* enc_b  = (const float*)d_in[3];
    const float* e_W1   = (const float*)d_in[4];
    const float* e_b1   = (const float*)d_in[5];
    const float* e_W2   = (const float*)d_in[6];
    const float* e_b2   = (const float*)d_in[7];
    const float* gWih   = (const float*)d_in[8];
    const float* gWhh   = (const float*)d_in[9];
    const float* gbih   = (const float*)d_in[10];
    const float* gbhh   = (const float*)d_in[11];
    const float* lWih   = (const float*)d_in[12];
    const float* lWhh   = (const float*)d_in[13];
    const float* lbih   = (const float*)d_in[14];
    const float* lbhh   = (const float*)d_in[15];
    const float* oW1    = (const float*)d_in[16];
    const float* ob1    = (const float*)d_in[17];
    const float* oW2    = (const float*)d_in[18];
    const float* ob2    = (const float*)d_in[19];
    const int*   eidx   = (const int*)d_in[20];
    const int*   batch  = (const int*)d_in[21];
    float* out = (float*)d_out;

    cudaFuncSetAttribute(k_msg_fused, cudaFuncAttributeMaxDynamicSharedMemorySize,
                         MSG_SMEM);

    // order chosen so the 4th launch (ncu capture target) is k_msg_fused
    k_packW2<<<(64 * 1024 + 255) / 256, 256>>>(e_W2);
    k_encode<<<(N_NODES + 255) / 256, 256>>>(nf, enc_W, enc_b);
    k_edgehid<<<(N_EDGES + 255) / 256, 256>>>(ef, e_W1, e_b1);

    for (int r = 0; r < 3; r++) {
        k_msg_fused<<<(N_EDGES + 127) / 128, 256, MSG_SMEM>>>(eidx, e_b2);
        k_gru<<<(N_NODES + 255) / 256, 256>>>(gWih, gWhh, gbih, gbhh);
    }

    k_offs<<<(N_NODES + 255) / 256, 256>>>(batch);
    k_s2s<<<(NG + 7) / 8, 256>>>(lWih, lWhh, lbih, lbhh, oW1, ob1, oW2, ob2, out);
}

// round 13
// speedup vs baseline: 1.4929x; 1.1392x over previous
#include <cuda_runtime.h>
#include <cuda_fp16.h>
#include <math_constants.h>

#define N_NODES 100000
#define N_EDGES 200000
#define NG      2000
#define H       32

typedef unsigned long long ull;

// ---------------- device scratch (alloc-free) ----------------
__device__ float  g_h[N_NODES * H];                 // node hidden fp32  12.8 MB
__device__ __half g_hh[N_NODES * H];                // node hidden fp16   6.4 MB
__device__ float  g_m[N_NODES * H];                 // aggregated msgs   12.8 MB
__device__ __half g_rh[(size_t)N_EDGES * 64];       // edge hidden fp16  25.6 MB
__device__ __half g_W2h[1024 * 64];                 // W2 fp16 transposed [n][k], 128 KB
__device__ __half g_GWh[192 * 64];                  // GRU weights fp16 block-diag [n][k], 24.6 KB
__device__ int    g_offs[NG + 1];                   // graph segment offsets

// ---------------- helpers ----------------
__device__ __forceinline__ void cpa16(void* dst, const void* src) {
    unsigned d = (unsigned)__cvta_generic_to_shared(dst);
    asm volatile("cp.async.cg.shared.global [%0], [%1], 16;" :: "r"(d), "l"(src));
}
__device__ __forceinline__ float warpMax(float v) {
    #pragma unroll
    for (int o = 16; o > 0; o >>= 1) v = fmaxf(v, __shfl_xor_sync(0xffffffffu, v, o));
    return v;
}
__device__ __forceinline__ float warpSum(float v) {
    #pragma unroll
    for (int o = 16; o > 0; o >>= 1) v += __shfl_xor_sync(0xffffffffu, v, o);
    return v;
}
__device__ __forceinline__ float sigm(float x) { return 1.0f / (1.0f + expf(-x)); }

// ---------------- W2 pack: g_W2h[n][k] = fp16(W2[k][n]) ----------------
__global__ void k_packW2(const float* __restrict__ W2) {
    int i = blockIdx.x * blockDim.x + threadIdx.x;
    if (i >= 64 * 1024) return;
    int k = i >> 10, n = i & 1023;
    g_W2h[n * 64 + k] = __float2half_rn(W2[i]);
}

// ---------------- GRU weight pack: block-diagonal [192][64] fp16 --------------
// n<96, k<32:  Wih[n][k]   (gi half, consumes m)
// n>=96,k>=32: Whh[n-96][k-32] (gh half, consumes h); zero elsewhere.
__global__ void k_packGW(const float* __restrict__ Wih, const float* __restrict__ Whh) {
    int i = blockIdx.x * blockDim.x + threadIdx.x;
    if (i >= 192 * 64) return;
    int n = i >> 6, k = i & 63;
    float v = 0.0f;
    if (n < 96 && k < 32) v = Wih[n * 32 + k];
    else if (n >= 96 && k >= 32) v = Whh[(n - 96) * 32 + (k - 32)];
    g_GWh[n * 64 + k] = __float2half_rn(v);
}

// ---------------- encoder: h = nf @ enc_W + enc_b; writes fp16 mirror; zeros m
__global__ void k_encode(const float* __restrict__ nf, const float* __restrict__ W,
                         const float* __restrict__ b) {
    __shared__ float sW[16 * 32];
    __shared__ float sb[32];
    int t = threadIdx.x;
    for (int i = t; i < 512; i += 256) sW[i] = W[i];
    if (t < 32) sb[t] = b[t];
    __syncthreads();
    int n = blockIdx.x * blockDim.x + t;
    if (n >= N_NODES) return;
    float x[16];
    const float4* p = (const float4*)(nf + (long long)n * 16);
    #pragma unroll
    for (int q = 0; q < 4; q++) {
        float4 v = p[q];
        x[q*4+0] = v.x; x[q*4+1] = v.y; x[q*4+2] = v.z; x[q*4+3] = v.w;
    }
    float hv[32];
    #pragma unroll
    for (int c = 0; c < 32; c++) {
        float acc = sb[c];
        #pragma unroll
        for (int d = 0; d < 16; d++) acc += x[d] * sW[d * 32 + c];
        hv[c] = acc;
    }
    float4* hp = (float4*)&g_h[n * 32];
    float4* mz = (float4*)&g_m[n * 32];
    __half2* hh = (__half2*)&g_hh[n * 32];
    #pragma unroll
    for (int q = 0; q < 8; q++) {
        hp[q] = make_float4(hv[q*4], hv[q*4+1], hv[q*4+2], hv[q*4+3]);
        mz[q] = make_float4(0.f, 0.f, 0.f, 0.f);
    }
    #pragma unroll
    for (int c2 = 0; c2 < 16; c2++)
        hh[c2] = __floats2half2_rn(hv[2*c2], hv[2*c2+1]);
}

// ---------------- edge hidden: rh = fp16(relu(ef @ e_W1 + e_b1)) ----------------
__global__ void k_edgehid(const float* __restrict__ ef, const float* __restrict__ W,
                          const float* __restrict__ b) {
    __shared__ float sW[8 * 64];
    __shared__ float sb[64];
    int t = threadIdx.x;
    for (int i = t; i < 512; i += 256) sW[i] = W[i];
    if (t < 64) sb[t] = b[t];
    __syncthreads();
    int e = blockIdx.x * blockDim.x + t;
    if (e >= N_EDGES) return;
    float x[8];
    const float4* p = (const float4*)(ef + (long long)e * 8);
    float4 v0 = p[0], v1 = p[1];
    x[0]=v0.x; x[1]=v0.y; x[2]=v0.z; x[3]=v0.w;
    x[4]=v1.x; x[5]=v1.y; x[6]=v1.z; x[7]=v1.w;
    float o[64];
    #pragma unroll
    for (int c = 0; c < 64; c++) {
        float acc = sb[c];
        #pragma unroll
        for (int d = 0; d < 8; d++) acc += x[d] * sW[d * 64 + c];
        o[c] = fmaxf(acc, 0.0f);
    }
    __half2* dst = (__half2*)&g_rh[(size_t)e * 64];
    #pragma unroll
    for (int c2 = 0; c2 < 32; c2++)
        dst[c2] = __floats2half2_rn(o[2 * c2], o[2 * c2 + 1]);
}

// ---------------- FUSED message pass: m[tgt] += (rh[e] @ W2 + b2) @ h[src] ------
#define ROWP 72
#define HSTR 40
#define MSG_SMEM 87040
__global__ void __launch_bounds__(256, 2) k_msg_fused(const int* __restrict__ ei,
                                                      const float* __restrict__ b2) {
    extern __shared__ unsigned char dsm[];
    __half* Rs   = (__half*)dsm;                       // [128][ROWP]
    __half* Wt0  = (__half*)(dsm + 18432);             // [128][ROWP]
    __half* Wt1  = (__half*)(dsm + 36864);             // [128][ROWP]
    __half* Hs   = (__half*)(dsm + 55296);             // [128][HSTR]
    float*  sMsg = (float*)(dsm + 65536);              // [128][33]
    int*    sTgt = (int*)(dsm + 82432);                // [128]
    float*  b2s  = (float*)(dsm + 82944);              // [1024]

    int t    = threadIdx.x;
    int lane = t & 31;
    int wid  = t >> 5;
    int e0   = blockIdx.x * 128;

    #pragma unroll
    for (int i = 0; i < 4; i++) {
        int g   = t + 256 * i;
        int row = g >> 3;
        int kg  = g & 7;
        cpa16(&Wt0[row * ROWP + kg * 8], &g_W2h[(size_t)row * 64 + kg * 8]);
    }
    asm volatile("cp.async.commit_group;");

    #pragma unroll
    for (int i = 0; i < 4; i++) {
        int g   = t + 256 * i;
        int row = g >> 3;
        int kg  = g & 7;
        uint4 v = make_uint4(0u, 0u, 0u, 0u);
        int e = e0 + row;
        if (e < N_EDGES) v = *(const uint4*)&g_rh[(size_t)e * 64 + kg * 8];
        *(uint4*)&Rs[row * ROWP + kg * 8] = v;
    }
    {
        int row = t >> 1, hf = t & 1;
        int e = e0 + row;
        bool ok = e < N_EDGES;
        int src = 0;
        if (ok) {
            src = ei[e];
            if (hf == 0) sTgt[row] = ei[N_EDGES + e];
        }
        const uint4* hp = (const uint4*)&g_hh[src * 32 + hf * 16];
        #pragma unroll
        for (int qq = 0; qq < 2; qq++) {
            uint4 v = ok ? hp[qq] : make_uint4(0u, 0u, 0u, 0u);
            *(uint4*)&Hs[row * HSTR + hf * 16 + qq * 8] = v;
        }
    }
    ((float4*)b2s)[t] = ((const float4*)b2)[t];

    asm volatile("cp.async.wait_group 0;");
    __syncthreads();

    int warpM = (wid & 1) * 64;
    int warpN = (wid >> 1) * 32;
    int aRow  = warpM + (lane & 15);
    int aColB = (lane >> 4) << 3;
    int bRow  = warpN + (lane & 7) + ((lane >> 4) << 3);
    int bColB = ((lane >> 3) & 1) << 3;

    #pragma unroll 1
    for (int c = 0; c < 8; c++) {
        const __half* Wtc = (c & 1) ? Wt1 : Wt0;
        if (c < 7) {
            __half* Wtn = (c & 1) ? Wt0 : Wt1;
            #pragma unroll
            for (int i = 0; i < 4; i++) {
                int g   = t + 256 * i;
                int row = g >> 3;
                int kg  = g & 7;
                cpa16(&Wtn[row * ROWP + kg * 8],
                      &g_W2h[(size_t)((c + 1) * 128 + row) * 64 + kg * 8]);
            }
            asm volatile("cp.async.commit_group;");
        }

        float acc[4][4][4];
        #pragma unroll
        for (int mt = 0; mt < 4; mt++)
            #pragma unroll
            for (int nt = 0; nt < 4; nt++)
                #pragma unroll
                for (int q = 0; q < 4; q++) acc[mt][nt][q] = 0.0f;

        #pragma unroll
        for (int ks = 0; ks < 4; ks++) {
            int k0 = ks * 16;
            unsigned a[4][4];
            #pragma unroll
            for (int mt = 0; mt < 4; mt++) {
                unsigned addr = (unsigned)__cvta_generic_to_shared(
                    &Rs[(aRow + mt * 16) * ROWP + k0 + aColB]);
                asm volatile("ldmatrix.sync.aligned.m8n8.x4.shared.b16 {%0,%1,%2,%3}, [%4];"
                             : "=r"(a[mt][0]), "=r"(a[mt][1]), "=r"(a[mt][2]), "=r"(a[mt][3])
                             : "r"(addr));
            }
            unsigned bf[4][2];
            #pragma unroll
            for (int p = 0; p < 2; p++) {
                unsigned addr = (unsigned)__cvta_generic_to_shared(
                    &Wtc[(bRow + p * 16) * ROWP + k0 + bColB]);
                asm volatile("ldmatrix.sync.aligned.m8n8.x4.shared.b16 {%0,%1,%2,%3}, [%4];"
                             : "=r"(bf[2*p][0]), "=r"(bf[2*p][1]),
                               "=r"(bf[2*p+1][0]), "=r"(bf[2*p+1][1])
                             : "r"(addr));
            }
            #pragma unroll
            for (int mt = 0; mt < 4; mt++)
                #pragma unroll
                for (int nt = 0; nt < 4; nt++) {
                    asm volatile(
                        "mma.sync.aligned.m16n8k16.row.col.f32.f16.f16.f32 "
                        "{%0,%1,%2,%3}, {%4,%5,%6,%7}, {%8,%9}, {%0,%1,%2,%3};"
                        : "+f"(acc[mt][nt][0]), "+f"(acc[mt][nt][1]),
                          "+f"(acc[mt][nt][2]), "+f"(acc[mt][nt][3])
                        : "r"(a[mt][0]), "r"(a[mt][1]), "r"(a[mt][2]), "r"(a[mt][3]),
                          "r"(bf[nt][0]), "r"(bf[nt][1]));
                }
        }

        #pragma unroll
        for (int nt = 0; nt < 4; nt++) {
            float2 bb = *(const float2*)&b2s[c * 128 + warpN + nt * 8 + (lane & 3) * 2];
            #pragma unroll
            for (int mt = 0; mt < 4; mt++) {
                acc[mt][nt][0] += bb.x; acc[mt][nt][1] += bb.y;
                acc[mt][nt][2] += bb.x; acc[mt][nt][3] += bb.y;
            }
        }

        int i_out = 4 * c + (wid >> 1);
        const __half2* Hs2 = (const __half2*)Hs;
        #pragma unroll
        for (int mt = 0; mt < 4; mt++) {
            #pragma unroll
            for (int qh = 0; qh < 2; qh++) {
                int rowl = warpM + mt * 16 + (lane >> 2) + 8 * qh;
                float partial = 0.0f;
                #pragma unroll
                for (int nt = 0; nt < 4; nt++) {
                    float2 hf2 = __half22float2(Hs2[rowl * (HSTR/2) + nt * 4 + (lane & 3)]);
                    partial += acc[mt][nt][2 * qh + 0] * hf2.x;
                    partial += acc[mt][nt][2 * qh + 1] * hf2.y;
                }
                partial += __shfl_xor_sync(0xffffffffu, partial, 1);
                partial += __shfl_xor_sync(0xffffffffu, partial, 2);
                if ((lane & 3) == 0)
                    sMsg[rowl * 33 + i_out] = partial;
            }
        }

        asm volatile("cp.async.wait_group 0;");
        __syncthreads();
    }

    #pragma unroll 1
    for (int idx = t; idx < 128 * 32; idx += 256) {
        int e = idx >> 5, i = idx & 31;
        if (e0 + e < N_EDGES)
            atomicAdd(&g_m[sTgt[e] * 32 + i], sMsg[e * 33 + i]);
    }
}

// ---------------- GRU via tensor cores: gates = [m|h] @ Gw^T, pointwise epilogue
// 64 nodes/block. X[64][64] fp16 (m|h), W [192][72] fp16 block-diag, fp32 acc.
// Gates staged in smem (biases added in pointwise), then GRU update; zeroes m.
// smem: Xs 9216 | Ws 27648 | sGate 64*196*4=50176 | sbi 384 | sbh 384 = 87808
#define GRU_SMEM 87808
__global__ void __launch_bounds__(256, 2) k_gru_mma(const float* __restrict__ bih,
                                                    const float* __restrict__ bhh) {
    extern __shared__ unsigned char dsm[];
    __half* Xs    = (__half*)dsm;                      // [64][72]
    __half* Ws    = (__half*)(dsm + 9216);             // [192][72]
    float*  sGate = (float*)(dsm + 36864);             // [64][196]
    float*  sbi   = (float*)(dsm + 87040);             // [96]
    float*  sbh   = (float*)(dsm + 87424);             // [96]

    int t = threadIdx.x, lane = t & 31, wid = t >> 5;
    int n0 = blockIdx.x * 64;

    // X tile: rows = nodes, cols 0-31 = fp16(m), cols 32-63 = hh
    {
        int row = t >> 2, quad = t & 3;
        int node = n0 + row;
        bool ok = node < N_NODES;
        if (quad < 2) {
            const float4* mp = (const float4*)&g_m[node * 32 + quad * 16];
            #pragma unroll
            for (int q = 0; q < 2; q++) {
                float4 v0 = ok ? mp[2*q]   : make_float4(0.f,0.f,0.f,0.f);
                float4 v1 = ok ? mp[2*q+1] : make_float4(0.f,0.f,0.f,0.f);
                uint4 u;
                __half2 h0 = __floats2half2_rn(v0.x, v0.y); u.x = *(unsigned*)&h0;
                __half2 h1 = __floats2half2_rn(v0.z, v0.w); u.y = *(unsigned*)&h1;
                __half2 h2 = __floats2half2_rn(v1.x, v1.y); u.z = *(unsigned*)&h2;
                __half2 h3 = __floats2half2_rn(v1.z, v1.w); u.w = *(unsigned*)&h3;
                *(uint4*)&Xs[row * 72 + quad * 16 + q * 8] = u;
            }
        } else {
            const uint4* hp = (const uint4*)&g_hh[node * 32 + (quad - 2) * 16];
            #pragma unroll
            for (int q = 0; q < 2; q++) {
                uint4 v = ok ? hp[q] : make_uint4(0u,0u,0u,0u);
                *(uint4*)&Xs[row * 72 + 32 + (quad - 2) * 16 + q * 8] = v;
            }
        }
    }
    // W tile [192][64] -> [192][72]
    #pragma unroll
    for (int j = 0; j < 6; j++) {
        int i = t + 256 * j;
        int rowW = i >> 3, kg = i & 7;
        *(uint4*)&Ws[rowW * 72 + kg * 8] = *(const uint4*)&g_GWh[rowW * 64 + kg * 8];
    }
    if (t < 96) sbi[t] = bih[t];
    else if (t < 192) sbh[t - 96] = bhh[t - 96];
    __syncthreads();

    int warpM = (wid & 1) * 32;
    int warpN = (wid >> 1) * 48;
    int aRow  = warpM + (lane & 15);
    int aColB = (lane >> 4) << 3;
    int bRow  = warpN + (lane & 7) + ((lane >> 4) << 3);
    int bColB = ((lane >> 3) & 1) << 3;

    float acc[2][6][4];
    #pragma unroll
    for (int mt = 0; mt < 2; mt++)
        #pragma unroll
        for (int nt = 0; nt < 6; nt++)
            #pragma unroll
            for (int q = 0; q < 4; q++) acc[mt][nt][q] = 0.0f;

    #pragma unroll
    for (int ks = 0; ks < 4; ks++) {
        int k0 = ks * 16;
        unsigned a[2][4];
        #pragma unroll
        for (int mt = 0; mt < 2; mt++) {
            unsigned addr = (unsigned)__cvta_generic_to_shared(
                &Xs[(aRow + mt * 16) * 72 + k0 + aColB]);
            asm volatile("ldmatrix.sync.aligned.m8n8.x4.shared.b16 {%0,%1,%2,%3}, [%4];"
                         : "=r"(a[mt][0]), "=r"(a[mt][1]), "=r"(a[mt][2]), "=r"(a[mt][3])
                         : "r"(addr));
        }
        unsigned bf[6][2];
        #pragma unroll
        for (int p = 0; p < 3; p++) {
            unsigned addr = (unsigned)__cvta_generic_to_shared(
                &Ws[(bRow + p * 16) * 72 + k0 + bColB]);
            asm volatile("ldmatrix.sync.aligned.m8n8.x4.shared.b16 {%0,%1,%2,%3}, [%4];"
                         : "=r"(bf[2*p][0]), "=r"(bf[2*p][1]),
                           "=r"(bf[2*p+1][0]), "=r"(bf[2*p+1][1])
                         : "r"(addr));
        }
        #pragma unroll
        for (int mt = 0; mt < 2; mt++)
            #pragma unroll
            for (int nt = 0; nt < 6; nt++) {
                asm volatile(
                    "mma.sync.aligned.m16n8k16.row.col.f32.f16.f16.f32 "
                    "{%0,%1,%2,%3}, {%4,%5,%6,%7}, {%8,%9}, {%0,%1,%2,%3};"
                    : "+f"(acc[mt][nt][0]), "+f"(acc[mt][nt][1]),
                      "+f"(acc[mt][nt][2]), "+f"(acc[mt][nt][3])
                    : "r"(a[mt][0]), "r"(a[mt][1]), "r"(a[mt][2]), "r"(a[mt][3]),
                      "r"(bf[nt][0]), "r"(bf[nt][1]));
            }
    }

    // stage gates to smem
    int r0base = warpM + (lane >> 2);
    #pragma unroll
    for (int nt = 0; nt < 6; nt++) {
        int col = warpN + nt * 8 + (lane & 3) * 2;
        #pragma unroll
        for (int mt = 0; mt < 2; mt++) {
            int r0 = r0base + mt * 16;
            *(float2*)&sGate[r0 * 196 + col] = make_float2(acc[mt][nt][0], acc[mt][nt][1]);
            *(float2*)&sGate[(r0 + 8) * 196 + col] = make_float2(acc[mt][nt][2], acc[mt][nt][3]);
        }
    }
    __syncthreads();

    // pointwise GRU update
    #pragma unroll 1
    for (int idx = t; idx < 64 * 32; idx += 256) {
        int nd = idx >> 5, k = idx & 31;
        int node = n0 + nd;
        if (node >= N_NODES) continue;
        const float* gr = &sGate[nd * 196];
        float gir = gr[k]        + sbi[k];
        float giz = gr[32 + k]   + sbi[32 + k];
        float gin = gr[64 + k]   + sbi[64 + k];
        float ghr = gr[96 + k]   + sbh[k];
        float ghz = gr[128 + k]  + sbh[32 + k];
        float ghn = gr[160 + k]  + sbh[64 + k];
        float r = sigm(gir + ghr);
        float z = sigm(giz + ghz);
        float nn = tanhf(gin + r * ghn);
        float hold = g_h[node * 32 + k];
        float hnew = (1.0f - z) * nn + z * hold;
        g_h[node * 32 + k]  = hnew;
        g_hh[node * 32 + k] = __float2half_rn(hnew);
        g_m[node * 32 + k]  = 0.0f;
    }
}

// ---------------- graph segment offsets (batch_indices sorted) ----------------
__global__ void k_offs(const int* __restrict__ batch) {
    int n = blockIdx.x * blockDim.x + threadIdx.x;
    if (n >= N_NODES) return;
    int b = batch[n];
    int prev = (n == 0) ? -1 : batch[n - 1];
    for (int g = prev + 1; g <= b; g++) g_offs[g] = n;
    if (n == N_NODES - 1)
        for (int g = b + 1; g <= NG; g++) g_offs[g] = N_NODES;
}

// ---------------- FUSED Set2Set: 4x(attend+LSTM) + output head, 1 warp/graph --
__global__ void __launch_bounds__(256) k_s2s(const float* __restrict__ lWih,
                                             const float* __restrict__ lWhh,
                                             const float* __restrict__ lbih,
                                             const float* __restrict__ lbhh,
                                             const float* __restrict__ oW1,
                                             const float* __restrict__ ob1,
                                             const float* __restrict__ oW2,
                                             const float* __restrict__ ob2,
                                             float* __restrict__ out) {
    __shared__ float sWa[128 * 33];
    __shared__ float sWb[128 * 33];
    __shared__ float sbias[128];
    __shared__ float sW1[64 * 32];
    __shared__ float sW2[96];
    __shared__ float sb1o[32];
    __shared__ float sb2o[3];
    int t = threadIdx.x, lane = t & 31, wid = t >> 5;

    for (int i = t; i < 128 * 32; i += 256) {
        int k = i >> 5, c = i & 31;
        sWa[k * 33 + c] = lWih[k * 64 + c] + lWhh[k * 32 + c];
        sWb[k * 33 + c] = lWih[k * 64 + 32 + c];
    }
    if (t < 128) sbias[t] = lbih[t] + lbhh[t];
    for (int i = t; i < 2048; i += 256) sW1[i] = oW1[i];
    if (t < 96) sW2[t] = oW2[t];
    if (t < 32) sb1o[t] = ob1[t];
    if (t < 3)  sb2o[t] = ob2[t];
    __syncthreads();

    int g = blockIdx.x * 8 + wid;
    if (g >= NG) return;
    int s = g_offs[g], tEnd = g_offs[g + 1];

    float sh = 0.0f, cst = 0.0f, rr = 0.0f;

    #pragma unroll 1
    for (int step = 0; step < 4; step++) {
        float q = sh;
        float maxv = -CUDART_INF_F, denom = 0.0f, racc = 0.0f;
        for (int base = s; base < tEnd; base += 32) {
            int n = base + lane;
            bool act = n < tEnd;
            int nn = act ? n : s;
            float rv[32];
            const float4* hp4 = (const float4*)&g_h[nn * 32];
            #pragma unroll
            for (int q4 = 0; q4 < 8; q4++) {
                float4 v = hp4[q4];
                rv[q4*4] = v.x; rv[q4*4+1] = v.y; rv[q4*4+2] = v.z; rv[q4*4+3] = v.w;
            }
            float ev = 0.0f;
            #pragma unroll
            for (int j = 0; j < 32; j++)
                ev += rv[j] * __shfl_sync(0xffffffffu, q, j);
            float e_n = act ? ev : -CUDART_INF_F;
            float cm = warpMax(e_n);
            float nm = fmaxf(maxv, cm);
            float scale = (maxv == -CUDART_INF_F) ? 0.0f : expf(maxv - nm);
            float p = act ? expf(e_n - nm) : 0.0f;
            float ps = warpSum(p);
            denom = denom * scale + ps;
            racc *= scale;
            maxv = nm;
            int cnt = min(32, tEnd - base);
            for (int n2 = 0; n2 < cnt; n2++) {
                float pn = __shfl_sync(0xffffffffu, p, n2);
                racc += pn * g_h[(base + n2) * 32 + lane];
            }
        }
        rr = (denom > 0.0f) ? (racc / denom) : 0.0f;

        float ai = sbias[lane];
        float af = sbias[32 + lane];
        float ag = sbias[64 + lane];
        float ao = sbias[96 + lane];
        #pragma unroll 1
        for (int c = 0; c < 32; c++) {
            float shv = __shfl_sync(0xffffffffu, sh, c);
            float rvv = __shfl_sync(0xffffffffu, rr, c);
            ai += shv * sWa[lane * 33 + c]        + rvv * sWb[lane * 33 + c];
            af += shv * sWa[(32 + lane) * 33 + c] + rvv * sWb[(32 + lane) * 33 + c];
            ag += shv * sWa[(64 + lane) * 33 + c] + rvv * sWb[(64 + lane) * 33 + c];
            ao += shv * sWa[(96 + lane) * 33 + c] + rvv * sWb[(96 + lane) * 33 + c];
        }
        float i_ = sigm(ai), f_ = sigm(af), gv = tanhf(ag), o_ = sigm(ao);
        cst = f_ * cst + i_ * gv;
        sh = o_ * tanhf(cst);
    }

    float hid = sb1o[lane];
    #pragma unroll 1
    for (int d = 0; d < 32; d++) {
        float shv = __shfl_sync(0xffffffffu, sh, d);
        float rvv = __shfl_sync(0xffffffffu, rr, d);
        hid += shv * sW1[d * 32 + lane] + rvv * sW1[(32 + d) * 32 + lane];
    }
    hid = fmaxf(hid, 0.0f);
    float o0 = hid * sW2[lane * 3 + 0];
    float o1 = hid * sW2[lane * 3 + 1];
    float o2 = hid * sW2[lane * 3 + 2];
    o0 = warpSum(o0); o1 = warpSum(o1); o2 = warpSum(o2);
    if (lane == 0) {
        out[g * 3 + 0] = o0 + sb2o[0];
        out[g * 3 + 1] = o1 + sb2o[1];
        out[g * 3 + 2] = o2 + sb2o[2];
    }
}

// ---------------- launch ----------------
extern "C" void kernel_launch(void* const* d_in, const int* in_sizes, int n_in,
                              void* d_out, int out_size) {
    const float* nf     = (const float*)d_in[0];
    const float* ef     = (const float*)d_in[1];
    const float* enc_W  = (const float*)d_in[2];
    const float* enc_b  = (const float*)d_in[3];
    const float* e_W1   = (const float*)d_in[4];
    const float* e_b1   = (const float*)d_in[5];
    const float* e_W2   = (const float*)d_in[6];
    const float* e_b2   = (const float*)d_in[7];
    const float* gWih   = (const float*)d_in[8];
    const float* gWhh   = (const float*)d_in[9];
    const float* gbih   = (const float*)d_in[10];
    const float* gbhh   = (const float*)d_in[11];
    const float* lWih   = (const float*)d_in[12];
    const float* lWhh   = (const float*)d_in[13];
    const float* lbih   = (const float*)d_in[14];
    const float* lbhh   = (const float*)d_in[15];
    const float* oW1    = (const float*)d_in[16];
    const float* ob1    = (const float*)d_in[17];
    const float* oW2    = (const float*)d_in[18];
    const float* ob2    = (const float*)d_in[19];
    const int*   eidx   = (const int*)d_in[20];
    const int*   batch  = (const int*)d_in[21];
    float* out = (float*)d_out;

    cudaFuncSetAttribute(k_msg_fused, cudaFuncAttributeMaxDynamicSharedMemorySize,
                         MSG_SMEM);
    cudaFuncSetAttribute(k_gru_mma, cudaFuncAttributeMaxDynamicSharedMemorySize,
                         GRU_SMEM);

    // order chosen so the 4th launch (ncu capture target) is k_msg_fused
    k_packW2<<<(64 * 1024 + 255) / 256, 256>>>(e_W2);
    k_encode<<<(N_NODES + 255) / 256, 256>>>(nf, enc_W, enc_b);
    k_edgehid<<<(N_EDGES + 255) / 256, 256>>>(ef, e_W1, e_b1);

    k_msg_fused<<<(N_EDGES + 127) / 128, 256, MSG_SMEM>>>(eidx, e_b2);
    k_packGW<<<(192 * 64 + 255) / 256, 256>>>(gWih, gWhh);
    k_gru_mma<<<(N_NODES + 63) / 64, 256, GRU_SMEM>>>(gbih, gbhh);

    for (int r = 1; r < 3; r++) {
        k_msg_fused<<<(N_EDGES + 127) / 128, 256, MSG_SMEM>>>(eidx, e_b2);
        k_gru_mma<<<(N_NODES + 63) / 64, 256, GRU_SMEM>>>(gbih, gbhh);
    }

    k_offs<<<(N_NODES + 255) / 256, 256>>>(batch);
    k_s2s<<<(NG + 7) / 8, 256>>>(lWih, lWhh, lbih, lbhh, oW1, ob1, oW2, ob2, out);
}